// round 15
// baseline (speedup 1.0000x reference)
#include <cuda_runtime.h>
#include <cuda_bf16.h>
#include <cuda_fp16.h>
#include <math.h>
#include <stdint.h>

#define BNUM 2
#define NSEQ 2048
#define DIMD 256
#define NHEAD 8
#define HD 32
#define FFD 1024
#define ROWS (BNUM*NSEQ)   // 4096

typedef __nv_bfloat16 bf16;

#define QSCALE (0.17677669529663687f * 1.4426950408889634f)
#define LOG2E  1.4426950408889634f

// ---------------- scratch (device globals, no allocation) ----------------
__device__ bf16  g_h  [ROWS*DIMD];            // LN1 out, ORIGINAL order (valid rows only)
__device__ bf16  g_q  [BNUM*NHEAD*NSEQ*HD];   // compacted rows (pad zeroed)
__device__ bf16  g_k  [BNUM*NHEAD*NSEQ*HD];
__device__ half  g_vT [BNUM*NHEAD*HD*NSEQ];   // [b][h][d][rc] compacted cols
__device__ float g_o0 [ROWS*DIMD];            // split-K partial O (compacted rows)
__device__ float g_o1 [ROWS*DIMD];
__device__ float g_l0 [BNUM*NHEAD*NSEQ];
__device__ float g_l1 [BNUM*NHEAD*NSEQ];
__device__ bf16  g_aoc[ROWS*DIMD];            // attention out, compacted
__device__ float g_x1c[ROWS*DIMD];            // x1, compacted
__device__ bf16  g_h2c[ROWS*DIMD];            // LN2 out, compacted
__device__ bf16  g_midc[ROWS*FFD];            // FFN mid, compacted
__device__ uint8_t g_codec[(size_t)BNUM*NSEQ*NSEQ];  // compacted codes
__device__ int   g_rl [BNUM*NSEQ];   // compacted -> original (pad -> 0)
__device__ int   g_pos[BNUM*NSEQ];   // original -> compacted (-1 masked)
__device__ int   g_nv [BNUM];
__device__ int   g_nvp[BNUM];        // padded to 128
__device__ bf16  g_wqkv [3*DIMD*DIMD];
__device__ bf16  g_wproj[DIMD*DIMD];
__device__ bf16  g_wf1  [FFD*DIMD];
__device__ bf16  g_wf2  [DIMD*FFD];

// ---------------- helpers ----------------
__device__ __forceinline__ void cpasync16(void* sdst, const void* gsrc){
    unsigned s = (unsigned)__cvta_generic_to_shared(sdst);
    asm volatile("cp.async.cg.shared.global [%0], [%1], 16;" :: "r"(s), "l"(gsrc));
}
#define CP_COMMIT() asm volatile("cp.async.commit_group;")
template<int N> __device__ __forceinline__ void cp_wait(){
    asm volatile("cp.async.wait_group %0;" :: "n"(N));
}

__device__ __forceinline__ void mma16(float* c,
    uint32_t a0, uint32_t a1, uint32_t a2, uint32_t a3,
    uint32_t b0, uint32_t b1)
{
    asm volatile("mma.sync.aligned.m16n8k16.row.col.f32.bf16.bf16.f32 "
        "{%0,%1,%2,%3}, {%4,%5,%6,%7}, {%8,%9}, {%0,%1,%2,%3};"
        : "+f"(c[0]), "+f"(c[1]), "+f"(c[2]), "+f"(c[3])
        : "r"(a0), "r"(a1), "r"(a2), "r"(a3), "r"(b0), "r"(b1));
}
__device__ __forceinline__ void mma16h(float* c,
    uint32_t a0, uint32_t a1, uint32_t a2, uint32_t a3,
    uint32_t b0, uint32_t b1)
{
    asm volatile("mma.sync.aligned.m16n8k16.row.col.f32.f16.f16.f32 "
        "{%0,%1,%2,%3}, {%4,%5,%6,%7}, {%8,%9}, {%0,%1,%2,%3};"
        : "+f"(c[0]), "+f"(c[1]), "+f"(c[2]), "+f"(c[3])
        : "r"(a0), "r"(a1), "r"(a2), "r"(a3), "r"(b0), "r"(b1));
}
__device__ __forceinline__ uint32_t hex2(uint32_t x){
    uint32_t y; asm("ex2.approx.f16x2 %0, %1;" : "=r"(y) : "r"(x)); return y;
}
__device__ __forceinline__ void ldsm4(uint32_t* r, uint32_t a){
    asm volatile("ldmatrix.sync.aligned.m8n8.x4.shared.b16 {%0,%1,%2,%3}, [%4];"
        : "=r"(r[0]), "=r"(r[1]), "=r"(r[2]), "=r"(r[3]) : "r"(a));
}
__device__ __forceinline__ void ldsm2(uint32_t* r, uint32_t a){
    asm volatile("ldmatrix.sync.aligned.m8n8.x2.shared.b16 {%0,%1}, [%2];"
        : "=r"(r[0]), "=r"(r[1]) : "r"(a));
}

// ---------------- LN body ----------------
__device__ __forceinline__ void ln_body(const float* __restrict__ x,
                                        const float* __restrict__ g,
                                        const float* __restrict__ b,
                                        bf16* __restrict__ y, int row,
                                        float* red, float* stat)
{
    int t = threadIdx.x;
    float v = x[(size_t)row * DIMD + t];
    float s = v;
    #pragma unroll
    for (int o = 16; o > 0; o >>= 1) s += __shfl_xor_sync(0xffffffffu, s, o);
    if ((t & 31) == 0) red[t >> 5] = s;
    __syncthreads();
    if (t < 32) {
        float r = (t < 8) ? red[t] : 0.f;
        #pragma unroll
        for (int o = 4; o > 0; o >>= 1) r += __shfl_xor_sync(0xffffffffu, r, o);
        if (t == 0) stat[0] = r * (1.0f / DIMD);
    }
    __syncthreads();
    float mu = stat[0];
    float d  = v - mu;
    float s2 = d * d;
    #pragma unroll
    for (int o = 16; o > 0; o >>= 1) s2 += __shfl_xor_sync(0xffffffffu, s2, o);
    if ((t & 31) == 0) red[t >> 5] = s2;
    __syncthreads();
    if (t < 32) {
        float r = (t < 8) ? red[t] : 0.f;
        #pragma unroll
        for (int o = 4; o > 0; o >>= 1) r += __shfl_xor_sync(0xffffffffu, r, o);
        if (t == 0) stat[1] = rsqrtf(r * (1.0f / DIMD) + 1e-5f);
    }
    __syncthreads();
    y[(size_t)row * DIMD + t] = __float2bfloat16(d * stat[1] * g[t] + b[t]);
}

// ---- setup: wconv + LN1(nm-guard) + masked-row copy + mask scan -----------
__global__ void __launch_bounds__(256)
setup_kernel(const float* __restrict__ w_qkv, const float* __restrict__ w_proj,
             const float* __restrict__ w_f1,  const float* __restrict__ w_f2,
             const int* __restrict__ nm,
             const float* __restrict__ x, const float* __restrict__ ln1_g,
             const float* __restrict__ ln1_b, float* __restrict__ out)
{
    __shared__ float tile[32][33];
    __shared__ float red[8];
    __shared__ float stat[2];
    __shared__ int wsum[8], wexcl[8], snv;
    int id = blockIdx.x;

    if (id < 768) {
        const float* W; bf16* Wt; int K, N; bool qs = false;
        if (id < 192)      { W = w_qkv;  Wt = g_wqkv;  K = 256;  N = 768;  qs = true; }
        else if (id < 256) { id -= 192; W = w_proj; Wt = g_wproj; K = 256;  N = 256; }
        else if (id < 512) { id -= 256; W = w_f1;   Wt = g_wf1;   K = 256;  N = 1024; }
        else               { id -= 512; W = w_f2;   Wt = g_wf2;   K = 1024; N = 256; }
        int tn = id % (N / 32), tk = id / (N / 32);
        int tx = threadIdx.x & 31, ty = threadIdx.x >> 5;
        #pragma unroll
        for (int r = 0; r < 4; ++r)
            tile[ty + r * 8][tx] = W[(size_t)(tk * 32 + ty + r * 8) * N + tn * 32 + tx];
        __syncthreads();
        float mul = (qs && tn < 8) ? QSCALE : 1.f;
        #pragma unroll
        for (int r = 0; r < 4; ++r) {
            int n = tn * 32 + ty + r * 8;
            Wt[(size_t)n * K + tk * 32 + tx] = __float2bfloat16(tile[tx][ty + r * 8] * mul);
        }
    } else if (id < 768 + ROWS) {
        int row = id - 768;
        if (nm[row] == 0) return;          // masked row never consumed
        ln_body(x, ln1_g, ln1_b, g_h, row, red, stat);
    } else if (id < 768 + 2 * ROWS) {
        int row = id - (768 + ROWS);
        if (nm[row] != 0) return;          // valid rows written by FFN2
        out[(size_t)row * DIMD + threadIdx.x] = x[(size_t)row * DIMD + threadIdx.x];
    } else {
        // ---- per-batch mask scan -> rowlist/pos/nv/nvp ----
        int b = id - (768 + 2 * ROWS), bN = b * NSEQ;
        int t = threadIdx.x, lane = t & 31, wid = t >> 5;
        int m[8], c = 0;
        #pragma unroll
        for (int k = 0; k < 8; ++k) { m[k] = nm[bN + t * 8 + k] != 0; c += m[k]; }
        int v = c;
        #pragma unroll
        for (int o = 1; o < 32; o <<= 1) {
            int u = __shfl_up_sync(0xffffffffu, v, o);
            if (lane >= o) v += u;
        }
        if (lane == 31) wsum[wid] = v;
        __syncthreads();
        if (t == 0) {
            int acc = 0;
            #pragma unroll
            for (int i = 0; i < 8; ++i) { wexcl[i] = acc; acc += wsum[i]; }
            g_nv[b] = acc;
            g_nvp[b] = (acc + 127) & ~127;
            snv = acc;
        }
        __syncthreads();
        int excl = v - c + wexcl[wid];
        #pragma unroll
        for (int k = 0; k < 8; ++k) {
            int n = t * 8 + k;
            if (m[k]) { g_rl[bN + excl] = n; g_pos[bN + n] = excl; excl++; }
            else      { g_pos[bN + n] = -1; }
        }
        for (int i = snv + t; i < NSEQ; i += 256) g_rl[bN + i] = 0;
    }
}

// ---- fused: code gather + pad zeroing (4096 blocks) | QKV GEMM (384) ------
__global__ void __launch_bounds__(256, 2)
gather_qkv(const int* __restrict__ et,
           const bf16* __restrict__ A, const float* __restrict__ bias)
{
    int bid = blockIdx.x;

    if (bid < 4096) {
        // ================= gather path =================
        int b = bid >> 11, ic = bid & 2047;
        int nvp = g_nvp[b], nv = g_nv[b];
        if (ic >= nvp) return;
        int bN = b * NSEQ;
        int tid = threadIdx.x;
        uint8_t* crow = g_codec + (size_t)(bN + ic) * NSEQ;

        if (ic >= nv) {
            for (int j = tid; j < nvp; j += 256) crow[j] = 0;
            int hh = tid >> 5, dd = tid & 31;
            g_q[((size_t)(b * NHEAD + hh) * NSEQ + ic) * HD + dd] = __float2bfloat16(0.f);
            g_k[((size_t)(b * NHEAD + hh) * NSEQ + ic) * HD + dd] = __float2bfloat16(0.f);
            g_vT[((size_t)(b * NHEAD + hh) * HD + dd) * NSEQ + ic] = __float2half(0.f);
            return;
        }
        int ri = g_rl[bN + ic];
        const int* er = et + (size_t)(bN + ri) * NSEQ;
        for (int jc = tid; jc < nvp; jc += 256) {
            uint8_t cv = 0;
            if (jc < nv) {
                int rj = g_rl[bN + jc];
                int e = er[rj];
                cv = (e != 0 || ri == rj) ? (uint8_t)(e + 1) : 0;
            }
            crow[jc] = cv;
        }
        return;
    }

    // ================= QKV path: BM=64, BN=128, NSTAGE=3 =================
    constexpr int BM = 64, BN = 128, KD = 256, NK = 4, NSTAGE = 3;
    constexpr int WTN = 32, NTN = 4, CB = 4;

    int g = bid - 4096;                  // 0..383, grid was (6,64)
    int rm = (g / 6) * BM, cn = (g % 6) * BN;
    int bb = rm >> 11;
    if ((rm & 2047) >= g_nvp[bb]) return;
    int nv_b = g_nv[bb];
    int bN0 = bb << 11;

    extern __shared__ __align__(16) bf16 gsm[];
    bf16* As = gsm;
    bf16* Bs = gsm + NSTAGE * BM * 72;

    int t = threadIdx.x, lane = t & 31, warp = t >> 5;
    int gid = lane >> 2, tig = lane & 3;
    int gq = lane >> 3, wq = lane & 7;
    int wm = warp % 2, wn = warp / 2;
    const bf16* Bg = g_wqkv + (size_t)cn * KD;

    int rl0 = g_rl[bN0 + (rm & 2047) + (t >> 3)];
    int rl1 = g_rl[bN0 + (rm & 2047) + (t >> 3) + 32];
    const bf16* Asrc0 = A + (size_t)(bN0 + rl0) * KD;
    const bf16* Asrc1 = A + (size_t)(bN0 + rl1) * KD;

    uint32_t As_u = (uint32_t)__cvta_generic_to_shared(As);
    uint32_t Bs_u = (uint32_t)__cvta_generic_to_shared(Bs);
    uint32_t offA = (uint32_t)(((gq & 1) * 8 + wq) * 144 + (gq >> 1) * 16);
    uint32_t offB = (uint32_t)(((gq >> 1) * 8 + wq) * 144 + (gq & 1) * 16);

    float acc[2][NTN][4];
    #pragma unroll
    for (int mi = 0; mi < 2; ++mi)
        #pragma unroll
        for (int nt = 0; nt < NTN; ++nt)
            #pragma unroll
            for (int q = 0; q < 4; ++q) acc[mi][nt][q] = 0.f;

    int aoff = (t & 7) * 8;
    auto load_stage = [&](int k0, int st) {
        bf16* Asd = As + st * BM * 72;
        bf16* Bsd = Bs + st * BN * 72;
        cpasync16(&Asd[(t >> 3) * 72 + aoff],        Asrc0 + k0 + aoff);
        cpasync16(&Asd[((t >> 3) + 32) * 72 + aoff], Asrc1 + k0 + aoff);
        #pragma unroll
        for (int i = 0; i < CB; ++i) {
            int c = t + i * 256, row = c >> 3, off = (c & 7) * 8;
            cpasync16(&Bsd[row * 72 + off], Bg + (size_t)row * KD + k0 + off);
        }
        CP_COMMIT();
    };

    load_stage(0, 0);
    load_stage(64, 1);
    for (int i = 0; i < NK; ++i) {
        int st = i % NSTAGE;
        if (i + 1 < NK) cp_wait<1>(); else cp_wait<0>();
        __syncthreads();
        if (i + 2 < NK) load_stage((i + 2) * 64, (i + 2) % NSTAGE);

        uint32_t Au = As_u + st * BM * 144;
        uint32_t Bu = Bs_u + st * BN * 144;
        #pragma unroll
        for (int ks = 0; ks < 4; ++ks) {
            uint32_t af[2][4];
            ldsm4(af[0], Au + (wm * 32     ) * 144 + ks * 32 + offA);
            ldsm4(af[1], Au + (wm * 32 + 16) * 144 + ks * 32 + offA);
            #pragma unroll
            for (int ntp = 0; ntp < NTN / 2; ++ntp) {
                uint32_t bbv[4];
                ldsm4(bbv, Bu + (wn * WTN + ntp * 16) * 144 + ks * 32 + offB);
                mma16(acc[0][2*ntp  ], af[0][0], af[0][1], af[0][2], af[0][3], bbv[0], bbv[1]);
                mma16(acc[1][2*ntp  ], af[1][0], af[1][1], af[1][2], af[1][3], bbv[0], bbv[1]);
                mma16(acc[0][2*ntp+1], af[0][0], af[0][1], af[0][2], af[0][3], bbv[2], bbv[3]);
                mma16(acc[1][2*ntp+1], af[1][0], af[1][1], af[1][2], af[1][3], bbv[2], bbv[3]);
            }
        }
    }

    // ---- epilogue: scatter q/k/vT at compacted rows ----
    #pragma unroll
    for (int mi = 0; mi < 2; ++mi) {
        #pragma unroll
        for (int half_i = 0; half_i < 2; ++half_i) {
            int r = rm + wm * 32 + mi * 16 + gid + half_i * 8;
            int rcl = r & 2047;
            if (rcl >= nv_b) continue;
            #pragma unroll
            for (int nt = 0; nt < NTN; ++nt) {
                int c = cn + wn * WTN + nt * 8 + tig * 2;
                float bmul = (c < DIMD) ? QSCALE : 1.f;
                float v0 = acc[mi][nt][half_i * 2 + 0] + bias[c] * bmul;
                float v1 = acc[mi][nt][half_i * 2 + 1] + bias[c + 1] * bmul;
                int part = c >> 8, hh = (c >> 5) & 7, dd = c & 31;
                if (part == 2) {
                    size_t base = ((size_t)(bb * NHEAD + hh) * HD + dd) * NSEQ + rcl;
                    g_vT[base]        = __float2half_rn(v0);
                    g_vT[base + NSEQ] = __float2half_rn(v1);
                } else {
                    bf16* dst = (part == 0) ? g_q : g_k;
                    __nv_bfloat162 pv = __floats2bfloat162_rn(v0, v1);
                    *(__nv_bfloat162*)&dst[((size_t)(bb * NHEAD + hh) * NSEQ + rcl) * HD + dd] = pv;
                }
            }
        }
    }
}

// ---------------- LN2 (compacted, guarded) ----------------
__global__ void ln2_kernel(const float* __restrict__ x,
                           const float* __restrict__ g,
                           const float* __restrict__ b,
                           bf16* __restrict__ y)
{
    __shared__ float red[8];
    __shared__ float stat[2];
    int row = blockIdx.x;
    if ((row & 2047) >= g_nvp[row >> 11]) return;
    ln_body(x, g, b, y, row, red, stat);
}

// ---------------- split-K merge + normalize -> compacted bf16 --------------
__global__ void __launch_bounds__(256)
merge_kernel()
{
    int rc = blockIdx.x;
    int b = rc >> 11, rcl = rc & 2047;
    if (rcl >= g_nv[b]) return;
    int t = threadIdx.x;
    int h = t >> 5;
    int li = (b * NHEAD + h) * NSEQ + rcl;
    float l = g_l0[li] + g_l1[li];
    float inv = l > 0.f ? 1.f / l : 0.f;
    size_t o = (size_t)rc * DIMD + t;
    g_aoc[o] = __float2bfloat16((g_o0[o] + g_o1[o]) * inv);
}

// ---------------- bf16 MMA GEMM, BK=64, NSTAGE-deep cp.async, ldmatrix -----
// MODE 1: proj  MODE 2: ffn1  MODE 3: ffn2
template<int BM, int BN, int KD, int NT, int MODE, int NSTAGE>
__global__ void __launch_bounds__(256, 2)
mma_gemm(const bf16* __restrict__ A, const bf16* __restrict__ Wt,
         const float* __restrict__ bias, const float* __restrict__ extra,
         float* __restrict__ outf, bf16* __restrict__ outb)
{
    constexpr int WM  = BM / 32;
    constexpr int WN  = 8 / WM;
    constexpr int WTN = BN / WN;
    constexpr int NTN = WTN / 8;
    constexpr int CB  = BN / 32;
    constexpr int NK  = KD / 64;

    int rm = blockIdx.y * BM, cn = blockIdx.x * BN;
    int bb = rm >> 11;
    if ((rm & 2047) >= g_nvp[bb]) return;
    int nv_b = g_nv[bb];
    int bN0 = bb << 11;

    extern __shared__ __align__(16) bf16 gsm[];
    bf16* As = gsm;
    bf16* Bs = gsm + NSTAGE * BM * 72;

    int t = threadIdx.x, lane = t & 31, warp = t >> 5;
    int gid = lane >> 2, tig = lane & 3;
    int gq = lane >> 3, wq = lane & 7;
    int wm = warp % WM, wn = warp / WM;
    const bf16* Bg = Wt + (size_t)cn * KD;

    const bf16* Asrc0 = A + (size_t)(rm + (t >> 3)) * KD;
    const bf16* Asrc1 = A + (size_t)(rm + (t >> 3) + 32) * KD;

    uint32_t As_u = (uint32_t)__cvta_generic_to_shared(As);
    uint32_t Bs_u = (uint32_t)__cvta_generic_to_shared(Bs);
    uint32_t offA = (uint32_t)(((gq & 1) * 8 + wq) * 144 + (gq >> 1) * 16);
    uint32_t offB = (uint32_t)(((gq >> 1) * 8 + wq) * 144 + (gq & 1) * 16);

    float acc[2][NTN][4];
    #pragma unroll
    for (int mi = 0; mi < 2; ++mi)
        #pragma unroll
        for (int nt = 0; nt < NTN; ++nt)
            #pragma unroll
            for (int q = 0; q < 4; ++q) acc[mi][nt][q] = 0.f;

    int aoff = (t & 7) * 8;
    auto load_stage = [&](int k0, int st) {
        bf16* Asd = As + st * BM * 72;
        bf16* Bsd = Bs + st * BN * 72;
        cpasync16(&Asd[(t >> 3) * 72 + aoff],        Asrc0 + k0 + aoff);
        cpasync16(&Asd[((t >> 3) + 32) * 72 + aoff], Asrc1 + k0 + aoff);
        #pragma unroll
        for (int i = 0; i < CB; ++i) {
            int c = t + i * 256, row = c >> 3, off = (c & 7) * 8;
            cpasync16(&Bsd[row * 72 + off], Bg + (size_t)row * KD + k0 + off);
        }
        CP_COMMIT();
    };

    #pragma unroll
    for (int p = 0; p < NSTAGE - 1; ++p)
        if (p < NK) load_stage(p * 64, p);

    for (int i = 0; i < NK; ++i) {
        int st = i % NSTAGE;
        int infl = ((i + NSTAGE - 1 < NK) ? (i + NSTAGE - 1) : NK) - i - 1;
        if (NSTAGE >= 4 && infl >= 2) cp_wait<2>();
        else if (infl == 1) cp_wait<1>();
        else cp_wait<0>();
        __syncthreads();
        if (i + NSTAGE - 1 < NK) load_stage((i + NSTAGE - 1) * 64, (i + NSTAGE - 1) % NSTAGE);

        uint32_t Au = As_u + st * BM * 144;
        uint32_t Bu = Bs_u + st * BN * 144;
        #pragma unroll
        for (int ks = 0; ks < 4; ++ks) {
            uint32_t af[2][4];
            ldsm4(af[0], Au + (wm * 32     ) * 144 + ks * 32 + offA);
            ldsm4(af[1], Au + (wm * 32 + 16) * 144 + ks * 32 + offA);
            #pragma unroll
            for (int ntp = 0; ntp < NTN / 2; ++ntp) {
                uint32_t bbv[4];
                ldsm4(bbv, Bu + (wn * WTN + ntp * 16) * 144 + ks * 32 + offB);
                mma16(acc[0][2*ntp  ], af[0][0], af[0][1], af[0][2], af[0][3], bbv[0], bbv[1]);
                mma16(acc[1][2*ntp  ], af[1][0], af[1][1], af[1][2], af[1][3], bbv[0], bbv[1]);
                mma16(acc[0][2*ntp+1], af[0][0], af[0][1], af[0][2], af[0][3], bbv[2], bbv[3]);
                mma16(acc[1][2*ntp+1], af[1][0], af[1][1], af[1][2], af[1][3], bbv[2], bbv[3]);
            }
        }
    }
    __syncthreads();

    // ---- epilogue ----
    #pragma unroll
    for (int mi = 0; mi < 2; ++mi) {
        #pragma unroll
        for (int half_i = 0; half_i < 2; ++half_i) {
            int r = rm + wm * 32 + mi * 16 + gid + half_i * 8;
            int rcl = r & 2047;
            int norig = 0;
            if (MODE == 1 || MODE == 3) norig = g_rl[bN0 + rcl];
            #pragma unroll
            for (int nt = 0; nt < NTN; ++nt) {
                int c = cn + wn * WTN + nt * 8 + tig * 2;
                float v0 = acc[mi][nt][half_i * 2 + 0] + bias[c];
                float v1 = acc[mi][nt][half_i * 2 + 1] + bias[c + 1];
                if (MODE == 1) {
                    float2 ex = *(const float2*)&extra[(size_t)(bN0 + norig) * NT + c];
                    *(float2*)&outf[(size_t)r * NT + c] = make_float2(ex.x + v0, ex.y + v1);
                } else if (MODE == 2) {
                    float g0 = 0.5f * v0 * (1.f + erff(v0 * 0.70710678118654752f));
                    float g1 = 0.5f * v1 * (1.f + erff(v1 * 0.70710678118654752f));
                    *(__nv_bfloat162*)&outb[(size_t)r * NT + c] = __floats2bfloat162_rn(g0, g1);
                } else {
                    if (rcl < nv_b) {
                        float2 ex = *(const float2*)&extra[(size_t)r * NT + c];
                        *(float2*)&outf[(size_t)(bN0 + norig) * NT + c] =
                            make_float2(ex.x + v0, ex.y + v1);
                    }
                }
            }
        }
    }
}

// ---------------- compacted flash attention, split-K x2 ----------------
__global__ void __launch_bounds__(256, 2)
attn_mma(const float* __restrict__ ebt)
{
    extern __shared__ __align__(16) bf16 smb[];
    bf16* Qs  = smb;                         // 128*40
    bf16* Ks0 = Qs + 5120;                   // 3 stages x 128*40
    half* Vs0 = (half*)(Ks0 + 3 * 5120);     // 3 stages x 40*136
    float* tbl2 = (float*)(Vs0 + 3 * 5440);  // 16 f32
    __half2* tblp = (__half2*)(tbl2 + 16);   // 2314 pair-bias entries

    int tid = threadIdx.x, lane = tid & 31, warp = tid >> 5;
    int gid = lane >> 2, tig = lane & 3;
    int gq = lane >> 3, wq = lane & 7;
    int bid = blockIdx.x;
    int h = bid & 7, rb = (bid >> 3) & 15, s = (bid >> 7) & 1, b = (bid >> 8) & 1;
    int r0 = rb * 128;
    const int bN = b * NSEQ;
    int w16 = warp * 16;

    int nvp = g_nvp[b];
    if (r0 >= nvp) return;
    int ntiles = nvp >> 7;
    int nh = (ntiles + 1) >> 1;
    int lo = s ? nh : 0;
    int hi = s ? ntiles : nh;
    if (lo >= hi) return;

    const bf16* qptr = g_q  + ((size_t)(b * NHEAD + h) * NSEQ + r0) * HD;
    const bf16* kbh  = g_k  + (size_t)(b * NHEAD + h) * NSEQ * HD;
    const half* vT   = g_vT + (size_t)(b * NHEAD + h) * HD * NSEQ;

    uint32_t Qs_u = (uint32_t)__cvta_generic_to_shared(Qs);
    uint32_t Ks_u = (uint32_t)__cvta_generic_to_shared(Ks0);
    uint32_t Vs_u = (uint32_t)__cvta_generic_to_shared(Vs0);
    uint32_t offA = (uint32_t)(((gq & 1) * 8 + wq) * 80 + (gq >> 1) * 16);
    uint32_t offB = (uint32_t)(((gq >> 1) * 8 + wq) * 80 + (gq & 1) * 16);
    uint32_t offV = (uint32_t)(((gq >> 1) * 8 + wq) * 272 + (gq & 1) * 16);

    auto load_kv = [&](int kt, int st) {
        int j0 = kt * 128;
        bf16* Ksd = Ks0 + st * 5120;
        half* Vsd = Vs0 + st * 5440;
        #pragma unroll
        for (int i = 0; i < 2; ++i) {
            int c = tid + i * 256, row = c >> 2, off = (c & 3) * 8;
            cpasync16(&Ksd[row * 40 + off], kbh + (size_t)(j0 + row) * HD + off);
        }
        #pragma unroll
        for (int i = 0; i < 2; ++i) {
            int c = tid + i * 256, d = c >> 4, off = (c & 15) * 8;
            cpasync16(&Vsd[d * 136 + off], vT + (size_t)d * NSEQ + j0 + off);
        }
        CP_COMMIT();
    };

    load_kv(lo, 0);
    if (lo + 1 < hi) load_kv(lo + 1, 1);

    #pragma unroll
    for (int i = 0; i < 2; ++i) {
        int c = tid + i * 256, row = c >> 2, off = (c & 3) * 8;
        *(uint4*)&Qs[row * 40 + off] = *(const uint4*)(qptr + (size_t)row * HD + off);
    }
    for (int u = tid; u < 3 * 8 * 64; u += 256) {
        int stg = u / 512, rem = u % 512, rowe = rem / 64, col = rem % 64;
        uint32_t val = (rowe == 0) ? 0x3C003C00u : 0u;
        *(uint32_t*)&Vs0[stg * 5440 + (32 + rowe) * 136 + col * 2] = val;
    }
    if (tid < 16)
        tbl2[tid] = (tid == 0) ? -30000.f
                  : (tid < 10 ? ebt[(tid - 1) * NHEAD + h] * LOG2E : 0.f);
    __syncthreads();

    for (int idx = tid; idx < 2314; idx += 256)
        tblp[idx] = __floats2half2_rn(tbl2[idx & 15], tbl2[(idx >> 8) & 15]);
    __syncthreads();

    uint32_t qa[2][4];
    ldsm4(qa[0], Qs_u + w16 * 80 +  0 + offA);
    ldsm4(qa[1], Qs_u + w16 * 80 + 32 + offA);

    float oacc[5][4];
    #pragma unroll
    for (int nt = 0; nt < 5; ++nt)
        #pragma unroll
        for (int q = 0; q < 4; ++q) oacc[nt][q] = 0.f;

    const uint8_t* crow0 = g_codec + (size_t)(bN + r0 + w16 + gid    ) * NSEQ + tig * 2;
    const uint8_t* crow1 = g_codec + (size_t)(bN + r0 + w16 + gid + 8) * NSEQ + tig * 2;

    for (int kt = lo; kt < hi; ++kt) {
        int st = (kt - lo) % 3, j0 = kt * 128;

        uint32_t cc[16];
        #pragma unroll
        for (int nt = 0; nt < 16; ++nt) {
            uint32_t c0 = *(const unsigned short*)(crow0 + j0 + nt * 8);
            uint32_t c1 = *(const unsigned short*)(crow1 + j0 + nt * 8);
            cc[nt] = c0 | (c1 << 16);
        }

        if (kt + 1 < hi) cp_wait<1>(); else cp_wait<0>();
        __syncthreads();
        if (kt + 2 < hi) load_kv(kt + 2, (kt - lo + 2) % 3);

        uint32_t Ku = Ks_u + st * 10240;
        float sacc[16][4];
        #pragma unroll
        for (int nt = 0; nt < 16; ++nt)
            #pragma unroll
            for (int q = 0; q < 4; ++q) sacc[nt][q] = 0.f;
        #pragma unroll
        for (int ks = 0; ks < 2; ++ks) {
            #pragma unroll
            for (int ntp = 0; ntp < 8; ++ntp) {
                uint32_t kb[4];
                ldsm4(kb, Ku + ntp * 1280 + ks * 32 + offB);
                mma16(sacc[2*ntp  ], qa[ks][0], qa[ks][1], qa[ks][2], qa[ks][3], kb[0], kb[1]);
                mma16(sacc[2*ntp+1], qa[ks][0], qa[ks][1], qa[ks][2], qa[ks][3], kb[2], kb[3]);
            }
        }

        uint32_t Vu = Vs_u + st * 10880;
        #pragma unroll
        for (int ks2 = 0; ks2 < 8; ++ks2) {
            uint32_t vb[10];
            ldsm4(vb + 0, Vu +    0 + ks2 * 32 + offV);
            ldsm4(vb + 4, Vu + 4352 + ks2 * 32 + offV);
            ldsm2(vb + 8, Vu + 8704 + ks2 * 32 + offV);
            uint32_t pf[4];
            #pragma unroll
            for (int half_i = 0; half_i < 2; ++half_i) {
                int nt = 2 * ks2 + half_i;
                uint32_t c = cc[nt];
                __half2 s01 = __floats2half2_rn(sacc[nt][0], sacc[nt][1]);
                __half2 s23 = __floats2half2_rn(sacc[nt][2], sacc[nt][3]);
                s01 = __hadd2(s01, tblp[c & 0xffff]);
                s23 = __hadd2(s23, tblp[c >> 16]);
                pf[half_i * 2 + 0] = hex2(*(uint32_t*)&s01);
                pf[half_i * 2 + 1] = hex2(*(uint32_t*)&s23);
            }
            #pragma unroll
            for (int nt2 = 0; nt2 < 5; ++nt2)
                mma16h(oacc[nt2], pf[0], pf[1], pf[2], pf[3], vb[2*nt2], vb[2*nt2+1]);
        }
    }

    // ---- write split partials (unnormalized) ----
    float* pl = s ? g_l1 : g_l0;
    float* po = s ? g_o1 : g_o0;
    if (tig == 0) {
        int li = (b * NHEAD + h) * NSEQ + r0 + w16 + gid;
        pl[li]     = oacc[4][0];
        pl[li + 8] = oacc[4][2];
    }
    float* pod = po + (size_t)(bN + r0) * DIMD + h * HD;
    #pragma unroll
    for (int nt = 0; nt < 4; ++nt) {
        int d = nt * 8 + tig * 2;
        *(float2*)&pod[(size_t)(w16 + gid    ) * DIMD + d] = make_float2(oacc[nt][0], oacc[nt][1]);
        *(float2*)&pod[(size_t)(w16 + gid + 8) * DIMD + d] = make_float2(oacc[nt][2], oacc[nt][3]);
    }
}

// ---------------- launch ----------------
static void* sym_addr(const void* sym)
{
    void* p = nullptr;
    cudaGetSymbolAddress(&p, sym);
    return p;
}

extern "C" void kernel_launch(void* const* d_in, const int* in_sizes, int n_in,
                              void* d_out, int out_size)
{
    const float* x      = (const float*)d_in[0];
    const int*   etyp   = (const int*)  d_in[1];
    const int*   nmask  = (const int*)  d_in[2];
    const float* qkv_w  = (const float*)d_in[3];
    const float* qkv_b  = (const float*)d_in[4];
    const float* proj_w = (const float*)d_in[5];
    const float* proj_b = (const float*)d_in[6];
    const float* ebt    = (const float*)d_in[7];
    const float* ln1_g  = (const float*)d_in[8];
    const float* ln1_b  = (const float*)d_in[9];
    const float* ln2_g  = (const float*)d_in[10];
    const float* ln2_b  = (const float*)d_in[11];
    const float* ffn_w1 = (const float*)d_in[12];
    const float* ffn_b1 = (const float*)d_in[13];
    const float* ffn_w2 = (const float*)d_in[14];
    const float* ffn_b2 = (const float*)d_in[15];
    float* out = (float*)d_out;

    bf16*  ph    = (bf16*) sym_addr(g_h);
    bf16*  paoc  = (bf16*) sym_addr(g_aoc);
    float* px1c  = (float*)sym_addr(g_x1c);
    bf16*  ph2c  = (bf16*) sym_addr(g_h2c);
    bf16*  pmidc = (bf16*) sym_addr(g_midc);
    bf16*  pwproj= (bf16*) sym_addr(g_wproj);
    bf16*  pwf1  = (bf16*) sym_addr(g_wf1);
    bf16*  pwf2  = (bf16*) sym_addr(g_wf2);

    const int ATTN_SMEM  = 10240 + 30720 + 32640 + 64 + 9600;   // 83264
    const int GSM3_64_128 = 3 * (64 * 72 + 128 * 72) * 2;       // 82944
    const int GSM4_64_64  = 4 * (64 * 72 + 64 * 72) * 2;        // 73728
    cudaFuncSetAttribute(attn_mma, cudaFuncAttributeMaxDynamicSharedMemorySize, ATTN_SMEM);
    cudaFuncSetAttribute(gather_qkv, cudaFuncAttributeMaxDynamicSharedMemorySize, GSM3_64_128);
    cudaFuncSetAttribute(mma_gemm<64,64,DIMD,DIMD,1,4>,  cudaFuncAttributeMaxDynamicSharedMemorySize, GSM4_64_64);
    cudaFuncSetAttribute(mma_gemm<64,128,DIMD,FFD,2,3>,  cudaFuncAttributeMaxDynamicSharedMemorySize, GSM3_64_128);
    cudaFuncSetAttribute(mma_gemm<64,64,FFD,DIMD,3,4>,   cudaFuncAttributeMaxDynamicSharedMemorySize, GSM4_64_64);

    // 1) setup: weight convert + LN1(valid) + masked-row copy + mask scan
    setup_kernel<<<768 + 2 * ROWS + BNUM, 256>>>(qkv_w, proj_w, ffn_w1, ffn_w2,
                                                 nmask, x, ln1_g, ln1_b, out);
    // 2) fused: code gather + pad zero | QKV GEMM (both depend only on setup)
    gather_qkv<<<4096 + 384, 256, GSM3_64_128>>>(etyp, ph, qkv_b);
    // 3) attention, split-K x2, fp32 partials
    attn_mma<<<512, 256, ATTN_SMEM>>>(ebt);
    // 4) merge + normalize -> compacted bf16
    merge_kernel<<<ROWS, 256>>>();
    // 5) proj + residual -> x1c (compacted, 64x64 4-stage)
    mma_gemm<64, 64, DIMD, DIMD, 1, 4><<<dim3(4, 64), 256, GSM4_64_64>>>(
        paoc, pwproj, proj_b, x, px1c, nullptr);
    // 6) LN2 (compacted)
    ln2_kernel<<<ROWS, 256>>>(px1c, ln2_g, ln2_b, ph2c);
    // 7) FFN1 + GELU (compacted, 64x128 3-stage)
    mma_gemm<64, 128, DIMD, FFD, 2, 3><<<dim3(8, 64), 256, GSM3_64_128>>>(
        ph2c, pwf1, ffn_b1, nullptr, nullptr, pmidc);
    // 8) FFN2 + residual, scatter to out via rowlist (64x64 4-stage)
    mma_gemm<64, 64, FFD, DIMD, 3, 4><<<dim3(4, 64), 256, GSM4_64_64>>>(
        pmidc, pwf2, ffn_b2, px1c, out, nullptr);
}

// round 16
// speedup vs baseline: 1.0929x; 1.0929x over previous
#include <cuda_runtime.h>
#include <cuda_bf16.h>
#include <cuda_fp16.h>
#include <math.h>
#include <stdint.h>

#define BNUM 2
#define NSEQ 2048
#define DIMD 256
#define NHEAD 8
#define HD 32
#define FFD 1024
#define ROWS (BNUM*NSEQ)   // 4096

typedef __nv_bfloat16 bf16;

#define QSCALE (0.17677669529663687f * 1.4426950408889634f)
#define LOG2E  1.4426950408889634f

// ---------------- scratch (device globals, no allocation) ----------------
__device__ bf16  g_h  [ROWS*DIMD];            // LN1 out, ORIGINAL order (valid rows only)
__device__ bf16  g_q  [BNUM*NHEAD*NSEQ*HD];   // compacted rows (pad zeroed)
__device__ bf16  g_k  [BNUM*NHEAD*NSEQ*HD];
__device__ half  g_vT [BNUM*NHEAD*HD*NSEQ];   // [b][h][d][rc] compacted cols
__device__ float g_o0 [ROWS*DIMD];            // split-K partial O (compacted rows)
__device__ float g_o1 [ROWS*DIMD];
__device__ float g_l0 [BNUM*NHEAD*NSEQ];
__device__ float g_l1 [BNUM*NHEAD*NSEQ];
__device__ bf16  g_aoc[ROWS*DIMD];            // attention out, compacted
__device__ float g_x1c[ROWS*DIMD];            // x1, compacted
__device__ bf16  g_h2c[ROWS*DIMD];            // LN2 out, compacted
__device__ bf16  g_midc[ROWS*FFD];            // FFN mid, compacted
__device__ uint8_t g_codec[(size_t)BNUM*NSEQ*NSEQ];  // compacted codes
__device__ int   g_rl [BNUM*NSEQ];   // compacted -> original (pad -> 0)
__device__ int   g_pos[BNUM*NSEQ];   // original -> compacted (-1 masked)
__device__ int   g_nv [BNUM];
__device__ int   g_nvp[BNUM];        // padded to 128
__device__ bf16  g_wqkv [3*DIMD*DIMD];
__device__ bf16  g_wproj[DIMD*DIMD];
__device__ bf16  g_wf1  [FFD*DIMD];
__device__ bf16  g_wf2  [DIMD*FFD];

// ---------------- helpers ----------------
__device__ __forceinline__ void cpasync16(void* sdst, const void* gsrc){
    unsigned s = (unsigned)__cvta_generic_to_shared(sdst);
    asm volatile("cp.async.cg.shared.global [%0], [%1], 16;" :: "r"(s), "l"(gsrc));
}
#define CP_COMMIT() asm volatile("cp.async.commit_group;")
template<int N> __device__ __forceinline__ void cp_wait(){
    asm volatile("cp.async.wait_group %0;" :: "n"(N));
}

__device__ __forceinline__ void mma16(float* c,
    uint32_t a0, uint32_t a1, uint32_t a2, uint32_t a3,
    uint32_t b0, uint32_t b1)
{
    asm volatile("mma.sync.aligned.m16n8k16.row.col.f32.bf16.bf16.f32 "
        "{%0,%1,%2,%3}, {%4,%5,%6,%7}, {%8,%9}, {%0,%1,%2,%3};"
        : "+f"(c[0]), "+f"(c[1]), "+f"(c[2]), "+f"(c[3])
        : "r"(a0), "r"(a1), "r"(a2), "r"(a3), "r"(b0), "r"(b1));
}
__device__ __forceinline__ void mma16h(float* c,
    uint32_t a0, uint32_t a1, uint32_t a2, uint32_t a3,
    uint32_t b0, uint32_t b1)
{
    asm volatile("mma.sync.aligned.m16n8k16.row.col.f32.f16.f16.f32 "
        "{%0,%1,%2,%3}, {%4,%5,%6,%7}, {%8,%9}, {%0,%1,%2,%3};"
        : "+f"(c[0]), "+f"(c[1]), "+f"(c[2]), "+f"(c[3])
        : "r"(a0), "r"(a1), "r"(a2), "r"(a3), "r"(b0), "r"(b1));
}
__device__ __forceinline__ uint32_t hex2(uint32_t x){
    uint32_t y; asm("ex2.approx.f16x2 %0, %1;" : "=r"(y) : "r"(x)); return y;
}
__device__ __forceinline__ void ldsm4(uint32_t* r, uint32_t a){
    asm volatile("ldmatrix.sync.aligned.m8n8.x4.shared.b16 {%0,%1,%2,%3}, [%4];"
        : "=r"(r[0]), "=r"(r[1]), "=r"(r[2]), "=r"(r[3]) : "r"(a));
}
__device__ __forceinline__ void ldsm2(uint32_t* r, uint32_t a){
    asm volatile("ldmatrix.sync.aligned.m8n8.x2.shared.b16 {%0,%1}, [%2];"
        : "=r"(r[0]), "=r"(r[1]) : "r"(a));
}

// ---------------- LN body ----------------
__device__ __forceinline__ void ln_body(const float* __restrict__ x,
                                        const float* __restrict__ g,
                                        const float* __restrict__ b,
                                        bf16* __restrict__ y, int row,
                                        float* red, float* stat)
{
    int t = threadIdx.x;
    float v = x[(size_t)row * DIMD + t];
    float s = v;
    #pragma unroll
    for (int o = 16; o > 0; o >>= 1) s += __shfl_xor_sync(0xffffffffu, s, o);
    if ((t & 31) == 0) red[t >> 5] = s;
    __syncthreads();
    if (t < 32) {
        float r = (t < 8) ? red[t] : 0.f;
        #pragma unroll
        for (int o = 4; o > 0; o >>= 1) r += __shfl_xor_sync(0xffffffffu, r, o);
        if (t == 0) stat[0] = r * (1.0f / DIMD);
    }
    __syncthreads();
    float mu = stat[0];
    float d  = v - mu;
    float s2 = d * d;
    #pragma unroll
    for (int o = 16; o > 0; o >>= 1) s2 += __shfl_xor_sync(0xffffffffu, s2, o);
    if ((t & 31) == 0) red[t >> 5] = s2;
    __syncthreads();
    if (t < 32) {
        float r = (t < 8) ? red[t] : 0.f;
        #pragma unroll
        for (int o = 4; o > 0; o >>= 1) r += __shfl_xor_sync(0xffffffffu, r, o);
        if (t == 0) stat[1] = rsqrtf(r * (1.0f / DIMD) + 1e-5f);
    }
    __syncthreads();
    y[(size_t)row * DIMD + t] = __float2bfloat16(d * stat[1] * g[t] + b[t]);
}

// ---- setup: wconv + LN1(nm-guard) + masked-row copy + mask scan -----------
__global__ void __launch_bounds__(256)
setup_kernel(const float* __restrict__ w_qkv, const float* __restrict__ w_proj,
             const float* __restrict__ w_f1,  const float* __restrict__ w_f2,
             const int* __restrict__ nm,
             const float* __restrict__ x, const float* __restrict__ ln1_g,
             const float* __restrict__ ln1_b, float* __restrict__ out)
{
    __shared__ float tile[32][33];
    __shared__ float red[8];
    __shared__ float stat[2];
    __shared__ int wsum[8], wexcl[8], snv;
    int id = blockIdx.x;

    if (id < 768) {
        const float* W; bf16* Wt; int K, N; bool qs = false;
        if (id < 192)      { W = w_qkv;  Wt = g_wqkv;  K = 256;  N = 768;  qs = true; }
        else if (id < 256) { id -= 192; W = w_proj; Wt = g_wproj; K = 256;  N = 256; }
        else if (id < 512) { id -= 256; W = w_f1;   Wt = g_wf1;   K = 256;  N = 1024; }
        else               { id -= 512; W = w_f2;   Wt = g_wf2;   K = 1024; N = 256; }
        int tn = id % (N / 32), tk = id / (N / 32);
        int tx = threadIdx.x & 31, ty = threadIdx.x >> 5;
        #pragma unroll
        for (int r = 0; r < 4; ++r)
            tile[ty + r * 8][tx] = W[(size_t)(tk * 32 + ty + r * 8) * N + tn * 32 + tx];
        __syncthreads();
        float mul = (qs && tn < 8) ? QSCALE : 1.f;
        #pragma unroll
        for (int r = 0; r < 4; ++r) {
            int n = tn * 32 + ty + r * 8;
            Wt[(size_t)n * K + tk * 32 + tx] = __float2bfloat16(tile[tx][ty + r * 8] * mul);
        }
    } else if (id < 768 + ROWS) {
        int row = id - 768;
        if (nm[row] == 0) return;          // masked row never consumed
        ln_body(x, ln1_g, ln1_b, g_h, row, red, stat);
    } else if (id < 768 + 2 * ROWS) {
        int row = id - (768 + ROWS);
        if (nm[row] != 0) return;          // valid rows written by FFN2
        out[(size_t)row * DIMD + threadIdx.x] = x[(size_t)row * DIMD + threadIdx.x];
    } else {
        // ---- per-batch mask scan -> rowlist/pos/nv/nvp ----
        int b = id - (768 + 2 * ROWS), bN = b * NSEQ;
        int t = threadIdx.x, lane = t & 31, wid = t >> 5;
        int m[8], c = 0;
        #pragma unroll
        for (int k = 0; k < 8; ++k) { m[k] = nm[bN + t * 8 + k] != 0; c += m[k]; }
        int v = c;
        #pragma unroll
        for (int o = 1; o < 32; o <<= 1) {
            int u = __shfl_up_sync(0xffffffffu, v, o);
            if (lane >= o) v += u;
        }
        if (lane == 31) wsum[wid] = v;
        __syncthreads();
        if (t == 0) {
            int acc = 0;
            #pragma unroll
            for (int i = 0; i < 8; ++i) { wexcl[i] = acc; acc += wsum[i]; }
            g_nv[b] = acc;
            g_nvp[b] = (acc + 127) & ~127;
            snv = acc;
        }
        __syncthreads();
        int excl = v - c + wexcl[wid];
        #pragma unroll
        for (int k = 0; k < 8; ++k) {
            int n = t * 8 + k;
            if (m[k]) { g_rl[bN + excl] = n; g_pos[bN + n] = excl; excl++; }
            else      { g_pos[bN + n] = -1; }
        }
        for (int i = snv + t; i < NSEQ; i += 256) g_rl[bN + i] = 0;
    }
}

// ---------------- compacted code gather + pad zeroing (no smem) ------------
__global__ void __launch_bounds__(256)
gather_kernel(const int* __restrict__ et)
{
    int b = blockIdx.y, ic = blockIdx.x;
    int nvp = g_nvp[b], nv = g_nv[b];
    if (ic >= nvp) return;
    int bN = b * NSEQ;
    int tid = threadIdx.x;
    uint8_t* crow = g_codec + (size_t)(bN + ic) * NSEQ;

    if (ic >= nv) {
        for (int j = tid; j < nvp; j += 256) crow[j] = 0;
        int hh = tid >> 5, dd = tid & 31;
        g_q[((size_t)(b * NHEAD + hh) * NSEQ + ic) * HD + dd] = __float2bfloat16(0.f);
        g_k[((size_t)(b * NHEAD + hh) * NSEQ + ic) * HD + dd] = __float2bfloat16(0.f);
        g_vT[((size_t)(b * NHEAD + hh) * HD + dd) * NSEQ + ic] = __float2half(0.f);
        return;
    }
    int ri = g_rl[bN + ic];
    const int* er = et + (size_t)(bN + ri) * NSEQ;
    for (int jc = tid; jc < nvp; jc += 256) {
        uint8_t cv = 0;
        if (jc < nv) {
            int rj = g_rl[bN + jc];
            int e = er[rj];
            cv = (e != 0 || ri == rj) ? (uint8_t)(e + 1) : 0;
        }
        crow[jc] = cv;
    }
}

// ---------------- LN2 (compacted, guarded) ----------------
__global__ void ln2_kernel(const float* __restrict__ x,
                           const float* __restrict__ g,
                           const float* __restrict__ b,
                           bf16* __restrict__ y)
{
    __shared__ float red[8];
    __shared__ float stat[2];
    int row = blockIdx.x;
    if ((row & 2047) >= g_nvp[row >> 11]) return;
    ln_body(x, g, b, y, row, red, stat);
}

// ---------------- split-K merge + normalize (float4 vectorized) ------------
__global__ void __launch_bounds__(256)
merge_kernel()
{
    int idx = blockIdx.x * 256 + threadIdx.x;   // over ROWS*DIMD/4
    int rc = idx >> 6;                          // 64 float4 per row
    int b = rc >> 11, rcl = rc & 2047;
    if (rcl >= g_nv[b]) return;
    int dim4 = idx & 63;
    int h = dim4 >> 3;                          // 8 float4 per head
    int li = (b * NHEAD + h) * NSEQ + rcl;
    float l = g_l0[li] + g_l1[li];
    float inv = l > 0.f ? 1.f / l : 0.f;
    size_t o = (size_t)rc * DIMD + dim4 * 4;
    float4 a = *(const float4*)&g_o0[o];
    float4 c = *(const float4*)&g_o1[o];
    __nv_bfloat162 r0 = __floats2bfloat162_rn((a.x + c.x) * inv, (a.y + c.y) * inv);
    __nv_bfloat162 r1 = __floats2bfloat162_rn((a.z + c.z) * inv, (a.w + c.w) * inv);
    *(uint2*)&g_aoc[o] = make_uint2(*(uint32_t*)&r0, *(uint32_t*)&r1);
}

// ---------------- bf16 MMA GEMM, BK=64, NSTAGE-deep cp.async, ldmatrix -----
// MODE 0: qkv  MODE 1: proj  MODE 2: ffn1  MODE 3: ffn2
template<int BM, int BN, int KD, int NT, int MODE, int NSTAGE>
__global__ void __launch_bounds__(256, 2)
mma_gemm(const bf16* __restrict__ A, const bf16* __restrict__ Wt,
         const float* __restrict__ bias, const float* __restrict__ extra,
         float* __restrict__ outf, bf16* __restrict__ outb)
{
    constexpr int WM  = BM / 32;
    constexpr int WN  = 8 / WM;
    constexpr int WTN = BN / WN;
    constexpr int NTN = WTN / 8;
    constexpr int CB  = BN / 32;
    constexpr int NK  = KD / 64;

    int rm = blockIdx.y * BM, cn = blockIdx.x * BN;
    int bb = rm >> 11;
    if ((rm & 2047) >= g_nvp[bb]) return;
    int nv_b = g_nv[bb];
    int bN0 = bb << 11;

    extern __shared__ __align__(16) bf16 gsm[];
    bf16* As = gsm;
    bf16* Bs = gsm + NSTAGE * BM * 72;

    int t = threadIdx.x, lane = t & 31, warp = t >> 5;
    int gid = lane >> 2, tig = lane & 3;
    int gq = lane >> 3, wq = lane & 7;
    int wm = warp % WM, wn = warp / WM;
    const bf16* Bg = Wt + (size_t)cn * KD;

    const bf16* Asrc0;
    const bf16* Asrc1;
    if (MODE == 0) {
        int rl0 = g_rl[bN0 + (rm & 2047) + (t >> 3)];
        int rl1 = g_rl[bN0 + (rm & 2047) + (t >> 3) + 32];
        Asrc0 = A + (size_t)(bN0 + rl0) * KD;
        Asrc1 = A + (size_t)(bN0 + rl1) * KD;
    } else {
        Asrc0 = A + (size_t)(rm + (t >> 3)) * KD;
        Asrc1 = A + (size_t)(rm + (t >> 3) + 32) * KD;
    }

    uint32_t As_u = (uint32_t)__cvta_generic_to_shared(As);
    uint32_t Bs_u = (uint32_t)__cvta_generic_to_shared(Bs);
    uint32_t offA = (uint32_t)(((gq & 1) * 8 + wq) * 144 + (gq >> 1) * 16);
    uint32_t offB = (uint32_t)(((gq >> 1) * 8 + wq) * 144 + (gq & 1) * 16);

    float acc[2][NTN][4];
    #pragma unroll
    for (int mi = 0; mi < 2; ++mi)
        #pragma unroll
        for (int nt = 0; nt < NTN; ++nt)
            #pragma unroll
            for (int q = 0; q < 4; ++q) acc[mi][nt][q] = 0.f;

    int aoff = (t & 7) * 8;
    auto load_stage = [&](int k0, int st) {
        bf16* Asd = As + st * BM * 72;
        bf16* Bsd = Bs + st * BN * 72;
        cpasync16(&Asd[(t >> 3) * 72 + aoff],        Asrc0 + k0 + aoff);
        cpasync16(&Asd[((t >> 3) + 32) * 72 + aoff], Asrc1 + k0 + aoff);
        #pragma unroll
        for (int i = 0; i < CB; ++i) {
            int c = t + i * 256, row = c >> 3, off = (c & 7) * 8;
            cpasync16(&Bsd[row * 72 + off], Bg + (size_t)row * KD + k0 + off);
        }
        CP_COMMIT();
    };

    #pragma unroll
    for (int p = 0; p < NSTAGE - 1; ++p)
        if (p < NK) load_stage(p * 64, p);

    for (int i = 0; i < NK; ++i) {
        int st = i % NSTAGE;
        int infl = ((i + NSTAGE - 1 < NK) ? (i + NSTAGE - 1) : NK) - i - 1;
        if (NSTAGE >= 4 && infl >= 2) cp_wait<2>();
        else if (infl == 1) cp_wait<1>();
        else cp_wait<0>();
        __syncthreads();
        if (i + NSTAGE - 1 < NK) load_stage((i + NSTAGE - 1) * 64, (i + NSTAGE - 1) % NSTAGE);

        uint32_t Au = As_u + st * BM * 144;
        uint32_t Bu = Bs_u + st * BN * 144;
        #pragma unroll
        for (int ks = 0; ks < 4; ++ks) {
            uint32_t af[2][4];
            ldsm4(af[0], Au + (wm * 32     ) * 144 + ks * 32 + offA);
            ldsm4(af[1], Au + (wm * 32 + 16) * 144 + ks * 32 + offA);
            #pragma unroll
            for (int ntp = 0; ntp < NTN / 2; ++ntp) {
                uint32_t bbv[4];
                ldsm4(bbv, Bu + (wn * WTN + ntp * 16) * 144 + ks * 32 + offB);
                mma16(acc[0][2*ntp  ], af[0][0], af[0][1], af[0][2], af[0][3], bbv[0], bbv[1]);
                mma16(acc[1][2*ntp  ], af[1][0], af[1][1], af[1][2], af[1][3], bbv[0], bbv[1]);
                mma16(acc[0][2*ntp+1], af[0][0], af[0][1], af[0][2], af[0][3], bbv[2], bbv[3]);
                mma16(acc[1][2*ntp+1], af[1][0], af[1][1], af[1][2], af[1][3], bbv[2], bbv[3]);
            }
        }
    }
    __syncthreads();

    // ---- epilogue ----
    #pragma unroll
    for (int mi = 0; mi < 2; ++mi) {
        #pragma unroll
        for (int half_i = 0; half_i < 2; ++half_i) {
            int r = rm + wm * 32 + mi * 16 + gid + half_i * 8;
            int rcl = r & 2047;
            int norig = 0;
            if (MODE == 1 || MODE == 3) norig = g_rl[bN0 + rcl];
            #pragma unroll
            for (int nt = 0; nt < NTN; ++nt) {
                int c = cn + wn * WTN + nt * 8 + tig * 2;
                float bmul = (MODE == 0 && c < DIMD) ? QSCALE : 1.f;
                float v0 = acc[mi][nt][half_i * 2 + 0] + bias[c] * bmul;
                float v1 = acc[mi][nt][half_i * 2 + 1] + bias[c + 1] * bmul;
                if (MODE == 0) {
                    if (rcl < nv_b) {
                        int part = c >> 8, hh = (c >> 5) & 7, dd = c & 31;
                        if (part == 2) {
                            size_t base = ((size_t)(bb * NHEAD + hh) * HD + dd) * NSEQ + rcl;
                            g_vT[base]        = __float2half_rn(v0);
                            g_vT[base + NSEQ] = __float2half_rn(v1);
                        } else {
                            bf16* dst = (part == 0) ? g_q : g_k;
                            __nv_bfloat162 pv = __floats2bfloat162_rn(v0, v1);
                            *(__nv_bfloat162*)&dst[((size_t)(bb * NHEAD + hh) * NSEQ + rcl) * HD + dd] = pv;
                        }
                    }
                } else if (MODE == 1) {
                    float2 ex = *(const float2*)&extra[(size_t)(bN0 + norig) * NT + c];
                    *(float2*)&outf[(size_t)r * NT + c] = make_float2(ex.x + v0, ex.y + v1);
                } else if (MODE == 2) {
                    float g0 = 0.5f * v0 * (1.f + erff(v0 * 0.70710678118654752f));
                    float g1 = 0.5f * v1 * (1.f + erff(v1 * 0.70710678118654752f));
                    *(__nv_bfloat162*)&outb[(size_t)r * NT + c] = __floats2bfloat162_rn(g0, g1);
                } else {
                    if (rcl < nv_b) {
                        float2 ex = *(const float2*)&extra[(size_t)r * NT + c];
                        *(float2*)&outf[(size_t)(bN0 + norig) * NT + c] =
                            make_float2(ex.x + v0, ex.y + v1);
                    }
                }
            }
        }
    }
}

// ---------------- compacted flash attention, split-K x2 ----------------
__global__ void __launch_bounds__(256, 2)
attn_mma(const float* __restrict__ ebt)
{
    extern __shared__ __align__(16) bf16 smb[];
    bf16* Qs  = smb;                         // 128*40
    bf16* Ks0 = Qs + 5120;                   // 3 stages x 128*40
    half* Vs0 = (half*)(Ks0 + 3 * 5120);     // 3 stages x 40*136
    float* tbl2 = (float*)(Vs0 + 3 * 5440);  // 16 f32
    __half2* tblp = (__half2*)(tbl2 + 16);   // 2314 pair-bias entries

    int tid = threadIdx.x, lane = tid & 31, warp = tid >> 5;
    int gid = lane >> 2, tig = lane & 3;
    int gq = lane >> 3, wq = lane & 7;
    int bid = blockIdx.x;
    int h = bid & 7, rb = (bid >> 3) & 15, s = (bid >> 7) & 1, b = (bid >> 8) & 1;
    int r0 = rb * 128;
    const int bN = b * NSEQ;
    int w16 = warp * 16;

    int nvp = g_nvp[b];
    if (r0 >= nvp) return;
    int ntiles = nvp >> 7;
    int nh = (ntiles + 1) >> 1;
    int lo = s ? nh : 0;
    int hi = s ? ntiles : nh;
    if (lo >= hi) return;

    const bf16* qptr = g_q  + ((size_t)(b * NHEAD + h) * NSEQ + r0) * HD;
    const bf16* kbh  = g_k  + (size_t)(b * NHEAD + h) * NSEQ * HD;
    const half* vT   = g_vT + (size_t)(b * NHEAD + h) * HD * NSEQ;

    uint32_t Qs_u = (uint32_t)__cvta_generic_to_shared(Qs);
    uint32_t Ks_u = (uint32_t)__cvta_generic_to_shared(Ks0);
    uint32_t Vs_u = (uint32_t)__cvta_generic_to_shared(Vs0);
    uint32_t offA = (uint32_t)(((gq & 1) * 8 + wq) * 80 + (gq >> 1) * 16);
    uint32_t offB = (uint32_t)(((gq >> 1) * 8 + wq) * 80 + (gq & 1) * 16);
    uint32_t offV = (uint32_t)(((gq >> 1) * 8 + wq) * 272 + (gq & 1) * 16);

    auto load_kv = [&](int kt, int st) {
        int j0 = kt * 128;
        bf16* Ksd = Ks0 + st * 5120;
        half* Vsd = Vs0 + st * 5440;
        #pragma unroll
        for (int i = 0; i < 2; ++i) {
            int c = tid + i * 256, row = c >> 2, off = (c & 3) * 8;
            cpasync16(&Ksd[row * 40 + off], kbh + (size_t)(j0 + row) * HD + off);
        }
        #pragma unroll
        for (int i = 0; i < 2; ++i) {
            int c = tid + i * 256, d = c >> 4, off = (c & 15) * 8;
            cpasync16(&Vsd[d * 136 + off], vT + (size_t)d * NSEQ + j0 + off);
        }
        CP_COMMIT();
    };

    load_kv(lo, 0);
    if (lo + 1 < hi) load_kv(lo + 1, 1);

    #pragma unroll
    for (int i = 0; i < 2; ++i) {
        int c = tid + i * 256, row = c >> 2, off = (c & 3) * 8;
        *(uint4*)&Qs[row * 40 + off] = *(const uint4*)(qptr + (size_t)row * HD + off);
    }
    for (int u = tid; u < 3 * 8 * 64; u += 256) {
        int stg = u / 512, rem = u % 512, rowe = rem / 64, col = rem % 64;
        uint32_t val = (rowe == 0) ? 0x3C003C00u : 0u;
        *(uint32_t*)&Vs0[stg * 5440 + (32 + rowe) * 136 + col * 2] = val;
    }
    if (tid < 16)
        tbl2[tid] = (tid == 0) ? -30000.f
                  : (tid < 10 ? ebt[(tid - 1) * NHEAD + h] * LOG2E : 0.f);
    __syncthreads();

    for (int idx = tid; idx < 2314; idx += 256)
        tblp[idx] = __floats2half2_rn(tbl2[idx & 15], tbl2[(idx >> 8) & 15]);
    __syncthreads();

    uint32_t qa[2][4];
    ldsm4(qa[0], Qs_u + w16 * 80 +  0 + offA);
    ldsm4(qa[1], Qs_u + w16 * 80 + 32 + offA);

    float oacc[5][4];
    #pragma unroll
    for (int nt = 0; nt < 5; ++nt)
        #pragma unroll
        for (int q = 0; q < 4; ++q) oacc[nt][q] = 0.f;

    const uint8_t* crow0 = g_codec + (size_t)(bN + r0 + w16 + gid    ) * NSEQ + tig * 2;
    const uint8_t* crow1 = g_codec + (size_t)(bN + r0 + w16 + gid + 8) * NSEQ + tig * 2;

    for (int kt = lo; kt < hi; ++kt) {
        int st = (kt - lo) % 3, j0 = kt * 128;

        uint32_t cc[16];
        #pragma unroll
        for (int nt = 0; nt < 16; ++nt) {
            uint32_t c0 = *(const unsigned short*)(crow0 + j0 + nt * 8);
            uint32_t c1 = *(const unsigned short*)(crow1 + j0 + nt * 8);
            cc[nt] = c0 | (c1 << 16);
        }

        if (kt + 1 < hi) cp_wait<1>(); else cp_wait<0>();
        __syncthreads();
        if (kt + 2 < hi) load_kv(kt + 2, (kt - lo + 2) % 3);

        uint32_t Ku = Ks_u + st * 10240;
        float sacc[16][4];
        #pragma unroll
        for (int nt = 0; nt < 16; ++nt)
            #pragma unroll
            for (int q = 0; q < 4; ++q) sacc[nt][q] = 0.f;
        #pragma unroll
        for (int ks = 0; ks < 2; ++ks) {
            #pragma unroll
            for (int ntp = 0; ntp < 8; ++ntp) {
                uint32_t kb[4];
                ldsm4(kb, Ku + ntp * 1280 + ks * 32 + offB);
                mma16(sacc[2*ntp  ], qa[ks][0], qa[ks][1], qa[ks][2], qa[ks][3], kb[0], kb[1]);
                mma16(sacc[2*ntp+1], qa[ks][0], qa[ks][1], qa[ks][2], qa[ks][3], kb[2], kb[3]);
            }
        }

        uint32_t Vu = Vs_u + st * 10880;
        #pragma unroll
        for (int ks2 = 0; ks2 < 8; ++ks2) {
            uint32_t vb[10];
            ldsm4(vb + 0, Vu +    0 + ks2 * 32 + offV);
            ldsm4(vb + 4, Vu + 4352 + ks2 * 32 + offV);
            ldsm2(vb + 8, Vu + 8704 + ks2 * 32 + offV);
            uint32_t pf[4];
            #pragma unroll
            for (int half_i = 0; half_i < 2; ++half_i) {
                int nt = 2 * ks2 + half_i;
                uint32_t c = cc[nt];
                __half2 s01 = __floats2half2_rn(sacc[nt][0], sacc[nt][1]);
                __half2 s23 = __floats2half2_rn(sacc[nt][2], sacc[nt][3]);
                s01 = __hadd2(s01, tblp[c & 0xffff]);
                s23 = __hadd2(s23, tblp[c >> 16]);
                pf[half_i * 2 + 0] = hex2(*(uint32_t*)&s01);
                pf[half_i * 2 + 1] = hex2(*(uint32_t*)&s23);
            }
            #pragma unroll
            for (int nt2 = 0; nt2 < 5; ++nt2)
                mma16h(oacc[nt2], pf[0], pf[1], pf[2], pf[3], vb[2*nt2], vb[2*nt2+1]);
        }
    }

    // ---- write split partials (unnormalized) ----
    float* pl = s ? g_l1 : g_l0;
    float* po = s ? g_o1 : g_o0;
    if (tig == 0) {
        int li = (b * NHEAD + h) * NSEQ + r0 + w16 + gid;
        pl[li]     = oacc[4][0];
        pl[li + 8] = oacc[4][2];
    }
    float* pod = po + (size_t)(bN + r0) * DIMD + h * HD;
    #pragma unroll
    for (int nt = 0; nt < 4; ++nt) {
        int d = nt * 8 + tig * 2;
        *(float2*)&pod[(size_t)(w16 + gid    ) * DIMD + d] = make_float2(oacc[nt][0], oacc[nt][1]);
        *(float2*)&pod[(size_t)(w16 + gid + 8) * DIMD + d] = make_float2(oacc[nt][2], oacc[nt][3]);
    }
}

// ---------------- launch ----------------
static void* sym_addr(const void* sym)
{
    void* p = nullptr;
    cudaGetSymbolAddress(&p, sym);
    return p;
}

extern "C" void kernel_launch(void* const* d_in, const int* in_sizes, int n_in,
                              void* d_out, int out_size)
{
    const float* x      = (const float*)d_in[0];
    const int*   etyp   = (const int*)  d_in[1];
    const int*   nmask  = (const int*)  d_in[2];
    const float* qkv_w  = (const float*)d_in[3];
    const float* qkv_b  = (const float*)d_in[4];
    const float* proj_w = (const float*)d_in[5];
    const float* proj_b = (const float*)d_in[6];
    const float* ebt    = (const float*)d_in[7];
    const float* ln1_g  = (const float*)d_in[8];
    const float* ln1_b  = (const float*)d_in[9];
    const float* ln2_g  = (const float*)d_in[10];
    const float* ln2_b  = (const float*)d_in[11];
    const float* ffn_w1 = (const float*)d_in[12];
    const float* ffn_b1 = (const float*)d_in[13];
    const float* ffn_w2 = (const float*)d_in[14];
    const float* ffn_b2 = (const float*)d_in[15];
    float* out = (float*)d_out;

    bf16*  ph    = (bf16*) sym_addr(g_h);
    bf16*  paoc  = (bf16*) sym_addr(g_aoc);
    float* px1c  = (float*)sym_addr(g_x1c);
    bf16*  ph2c  = (bf16*) sym_addr(g_h2c);
    bf16*  pmidc = (bf16*) sym_addr(g_midc);
    bf16*  pwqkv = (bf16*) sym_addr(g_wqkv);
    bf16*  pwproj= (bf16*) sym_addr(g_wproj);
    bf16*  pwf1  = (bf16*) sym_addr(g_wf1);
    bf16*  pwf2  = (bf16*) sym_addr(g_wf2);

    const int ATTN_SMEM  = 10240 + 30720 + 32640 + 64 + 9600;   // 83264
    const int GSM3_64_128 = 3 * (64 * 72 + 128 * 72) * 2;       // 82944
    const int GSM4_64_64  = 4 * (64 * 72 + 64 * 72) * 2;        // 73728
    cudaFuncSetAttribute(attn_mma, cudaFuncAttributeMaxDynamicSharedMemorySize, ATTN_SMEM);
    cudaFuncSetAttribute(mma_gemm<64,128,DIMD,3*DIMD,0,3>, cudaFuncAttributeMaxDynamicSharedMemorySize, GSM3_64_128);
    cudaFuncSetAttribute(mma_gemm<64,64,DIMD,DIMD,1,4>,    cudaFuncAttributeMaxDynamicSharedMemorySize, GSM4_64_64);
    cudaFuncSetAttribute(mma_gemm<64,128,DIMD,FFD,2,3>,    cudaFuncAttributeMaxDynamicSharedMemorySize, GSM3_64_128);
    cudaFuncSetAttribute(mma_gemm<64,64,FFD,DIMD,3,4>,     cudaFuncAttributeMaxDynamicSharedMemorySize, GSM4_64_64);

    // 1) setup: weight convert + LN1(valid) + masked-row copy + mask scan
    setup_kernel<<<768 + 2 * ROWS + BNUM, 256>>>(qkv_w, proj_w, ffn_w1, ffn_w2,
                                                 nmask, x, ln1_g, ln1_b, out);
    // 2) compacted codes + pad zeroing (high-occupancy, no smem)
    gather_kernel<<<dim3(NSEQ, BNUM), 256>>>(etyp);
    // 3) QKV GEMM (64x128, rows gathered via rowlist, compacted scatter)
    mma_gemm<64, 128, DIMD, 3*DIMD, 0, 3><<<dim3(6, 64), 256, GSM3_64_128>>>(
        ph, pwqkv, qkv_b, nullptr, nullptr, nullptr);
    // 4) attention, split-K x2, fp32 partials
    attn_mma<<<512, 256, ATTN_SMEM>>>(ebt);
    // 5) merge + normalize -> compacted bf16 (float4 vectorized)
    merge_kernel<<<ROWS * DIMD / 1024, 256>>>();
    // 6) proj + residual -> x1c (compacted, 64x64 4-stage)
    mma_gemm<64, 64, DIMD, DIMD, 1, 4><<<dim3(4, 64), 256, GSM4_64_64>>>(
        paoc, pwproj, proj_b, x, px1c, nullptr);
    // 7) LN2 (compacted)
    ln2_kernel<<<ROWS, 256>>>(px1c, ln2_g, ln2_b, ph2c);
    // 8) FFN1 + GELU (compacted, 64x128 3-stage)
    mma_gemm<64, 128, DIMD, FFD, 2, 3><<<dim3(8, 64), 256, GSM3_64_128>>>(
        ph2c, pwf1, ffn_b1, nullptr, nullptr, pmidc);
    // 9) FFN2 + residual, scatter to out via rowlist (64x64 4-stage)
    mma_gemm<64, 64, FFD, DIMD, 3, 4><<<dim3(4, 64), 256, GSM4_64_64>>>(
        pmidc, pwf2, ffn_b2, px1c, out, nullptr);
}

// round 17
// speedup vs baseline: 1.1107x; 1.0162x over previous
#include <cuda_runtime.h>
#include <cuda_bf16.h>
#include <cuda_fp16.h>
#include <math.h>
#include <stdint.h>

#define BNUM 2
#define NSEQ 2048
#define DIMD 256
#define NHEAD 8
#define HD 32
#define FFD 1024
#define ROWS (BNUM*NSEQ)   // 4096

typedef __nv_bfloat16 bf16;

#define QSCALE (0.17677669529663687f * 1.4426950408889634f)
#define LOG2E  1.4426950408889634f

// ---------------- scratch (device globals, no allocation) ----------------
__device__ bf16  g_h  [ROWS*DIMD];            // LN1 out, ORIGINAL order (valid rows only)
__device__ bf16  g_q  [BNUM*NHEAD*NSEQ*HD];   // compacted rows (pad zeroed)
__device__ bf16  g_k  [BNUM*NHEAD*NSEQ*HD];
__device__ half  g_vT [BNUM*NHEAD*HD*NSEQ];   // [b][h][d][rc] compacted cols
__device__ float g_o0 [ROWS*DIMD];            // split-K partial O (compacted rows)
__device__ float g_o1 [ROWS*DIMD];
__device__ float g_l0 [BNUM*NHEAD*NSEQ];
__device__ float g_l1 [BNUM*NHEAD*NSEQ];
__device__ bf16  g_aoc[ROWS*DIMD];            // attention out, compacted
__device__ float g_x1c[ROWS*DIMD];            // x1, compacted
__device__ bf16  g_h2c[ROWS*DIMD];            // LN2 out, compacted
__device__ bf16  g_midc[ROWS*FFD];            // FFN mid, compacted
__device__ uint8_t g_codec[(size_t)BNUM*NSEQ*NSEQ];  // compacted codes
__device__ int   g_rl [BNUM*NSEQ];   // compacted -> original (pad -> 0)
__device__ int   g_pos[BNUM*NSEQ];   // original -> compacted (-1 masked)
__device__ int   g_nv [BNUM];
__device__ int   g_nvp[BNUM];        // padded to 128
__device__ bf16  g_wqkv [3*DIMD*DIMD];
__device__ bf16  g_wproj[DIMD*DIMD];
__device__ bf16  g_wf1  [FFD*DIMD];
__device__ bf16  g_wf2  [DIMD*FFD];

// ---------------- helpers ----------------
__device__ __forceinline__ void cpasync16(void* sdst, const void* gsrc){
    unsigned s = (unsigned)__cvta_generic_to_shared(sdst);
    asm volatile("cp.async.cg.shared.global [%0], [%1], 16;" :: "r"(s), "l"(gsrc));
}
#define CP_COMMIT() asm volatile("cp.async.commit_group;")
template<int N> __device__ __forceinline__ void cp_wait(){
    asm volatile("cp.async.wait_group %0;" :: "n"(N));
}

__device__ __forceinline__ void mma16(float* c,
    uint32_t a0, uint32_t a1, uint32_t a2, uint32_t a3,
    uint32_t b0, uint32_t b1)
{
    asm volatile("mma.sync.aligned.m16n8k16.row.col.f32.bf16.bf16.f32 "
        "{%0,%1,%2,%3}, {%4,%5,%6,%7}, {%8,%9}, {%0,%1,%2,%3};"
        : "+f"(c[0]), "+f"(c[1]), "+f"(c[2]), "+f"(c[3])
        : "r"(a0), "r"(a1), "r"(a2), "r"(a3), "r"(b0), "r"(b1));
}
__device__ __forceinline__ void mma16h(float* c,
    uint32_t a0, uint32_t a1, uint32_t a2, uint32_t a3,
    uint32_t b0, uint32_t b1)
{
    asm volatile("mma.sync.aligned.m16n8k16.row.col.f32.f16.f16.f32 "
        "{%0,%1,%2,%3}, {%4,%5,%6,%7}, {%8,%9}, {%0,%1,%2,%3};"
        : "+f"(c[0]), "+f"(c[1]), "+f"(c[2]), "+f"(c[3])
        : "r"(a0), "r"(a1), "r"(a2), "r"(a3), "r"(b0), "r"(b1));
}
__device__ __forceinline__ uint32_t hex2(uint32_t x){
    uint32_t y; asm("ex2.approx.f16x2 %0, %1;" : "=r"(y) : "r"(x)); return y;
}
__device__ __forceinline__ void ldsm4(uint32_t* r, uint32_t a){
    asm volatile("ldmatrix.sync.aligned.m8n8.x4.shared.b16 {%0,%1,%2,%3}, [%4];"
        : "=r"(r[0]), "=r"(r[1]), "=r"(r[2]), "=r"(r[3]) : "r"(a));
}
__device__ __forceinline__ void ldsm2(uint32_t* r, uint32_t a){
    asm volatile("ldmatrix.sync.aligned.m8n8.x2.shared.b16 {%0,%1}, [%2];"
        : "=r"(r[0]), "=r"(r[1]) : "r"(a));
}

// ---------------- LN body ----------------
__device__ __forceinline__ void ln_body(const float* __restrict__ x,
                                        const float* __restrict__ g,
                                        const float* __restrict__ b,
                                        bf16* __restrict__ y, int row,
                                        float* red, float* stat)
{
    int t = threadIdx.x;
    float v = x[(size_t)row * DIMD + t];
    float s = v;
    #pragma unroll
    for (int o = 16; o > 0; o >>= 1) s += __shfl_xor_sync(0xffffffffu, s, o);
    if ((t & 31) == 0) red[t >> 5] = s;
    __syncthreads();
    if (t < 32) {
        float r = (t < 8) ? red[t] : 0.f;
        #pragma unroll
        for (int o = 4; o > 0; o >>= 1) r += __shfl_xor_sync(0xffffffffu, r, o);
        if (t == 0) stat[0] = r * (1.0f / DIMD);
    }
    __syncthreads();
    float mu = stat[0];
    float d  = v - mu;
    float s2 = d * d;
    #pragma unroll
    for (int o = 16; o > 0; o >>= 1) s2 += __shfl_xor_sync(0xffffffffu, s2, o);
    if ((t & 31) == 0) red[t >> 5] = s2;
    __syncthreads();
    if (t < 32) {
        float r = (t < 8) ? red[t] : 0.f;
        #pragma unroll
        for (int o = 4; o > 0; o >>= 1) r += __shfl_xor_sync(0xffffffffu, r, o);
        if (t == 0) stat[1] = rsqrtf(r * (1.0f / DIMD) + 1e-5f);
    }
    __syncthreads();
    y[(size_t)row * DIMD + t] = __float2bfloat16(d * stat[1] * g[t] + b[t]);
}

// ---- setup: wconv + LN1(nm-guard) + masked-row copy + mask scan -----------
__global__ void __launch_bounds__(256)
setup_kernel(const float* __restrict__ w_qkv, const float* __restrict__ w_proj,
             const float* __restrict__ w_f1,  const float* __restrict__ w_f2,
             const int* __restrict__ nm,
             const float* __restrict__ x, const float* __restrict__ ln1_g,
             const float* __restrict__ ln1_b, float* __restrict__ out)
{
    __shared__ float tile[32][33];
    __shared__ float red[8];
    __shared__ float stat[2];
    __shared__ int wsum[8], wexcl[8], snv;
    int id = blockIdx.x;

    if (id < 768) {
        const float* W; bf16* Wt; int K, N; bool qs = false;
        if (id < 192)      { W = w_qkv;  Wt = g_wqkv;  K = 256;  N = 768;  qs = true; }
        else if (id < 256) { id -= 192; W = w_proj; Wt = g_wproj; K = 256;  N = 256; }
        else if (id < 512) { id -= 256; W = w_f1;   Wt = g_wf1;   K = 256;  N = 1024; }
        else               { id -= 512; W = w_f2;   Wt = g_wf2;   K = 1024; N = 256; }
        int tn = id % (N / 32), tk = id / (N / 32);
        int tx = threadIdx.x & 31, ty = threadIdx.x >> 5;
        #pragma unroll
        for (int r = 0; r < 4; ++r)
            tile[ty + r * 8][tx] = W[(size_t)(tk * 32 + ty + r * 8) * N + tn * 32 + tx];
        __syncthreads();
        float mul = (qs && tn < 8) ? QSCALE : 1.f;
        #pragma unroll
        for (int r = 0; r < 4; ++r) {
            int n = tn * 32 + ty + r * 8;
            Wt[(size_t)n * K + tk * 32 + tx] = __float2bfloat16(tile[tx][ty + r * 8] * mul);
        }
    } else if (id < 768 + ROWS) {
        int row = id - 768;
        if (nm[row] == 0) return;
        ln_body(x, ln1_g, ln1_b, g_h, row, red, stat);
    } else if (id < 768 + 2 * ROWS) {
        int row = id - (768 + ROWS);
        if (nm[row] != 0) return;
        out[(size_t)row * DIMD + threadIdx.x] = x[(size_t)row * DIMD + threadIdx.x];
    } else {
        int b = id - (768 + 2 * ROWS), bN = b * NSEQ;
        int t = threadIdx.x, lane = t & 31, wid = t >> 5;
        int m[8], c = 0;
        #pragma unroll
        for (int k = 0; k < 8; ++k) { m[k] = nm[bN + t * 8 + k] != 0; c += m[k]; }
        int v = c;
        #pragma unroll
        for (int o = 1; o < 32; o <<= 1) {
            int u = __shfl_up_sync(0xffffffffu, v, o);
            if (lane >= o) v += u;
        }
        if (lane == 31) wsum[wid] = v;
        __syncthreads();
        if (t == 0) {
            int acc = 0;
            #pragma unroll
            for (int i = 0; i < 8; ++i) { wexcl[i] = acc; acc += wsum[i]; }
            g_nv[b] = acc;
            g_nvp[b] = (acc + 127) & ~127;
            snv = acc;
        }
        __syncthreads();
        int excl = v - c + wexcl[wid];
        #pragma unroll
        for (int k = 0; k < 8; ++k) {
            int n = t * 8 + k;
            if (m[k]) { g_rl[bN + excl] = n; g_pos[bN + n] = excl; excl++; }
            else      { g_pos[bN + n] = -1; }
        }
        for (int i = snv + t; i < NSEQ; i += 256) g_rl[bN + i] = 0;
    }
}

// ---------------- compacted code gather + pad zeroing (no smem) ------------
__global__ void __launch_bounds__(256)
gather_kernel(const int* __restrict__ et)
{
    int b = blockIdx.y, ic = blockIdx.x;
    int nvp = g_nvp[b], nv = g_nv[b];
    if (ic >= nvp) return;
    int bN = b * NSEQ;
    int tid = threadIdx.x;
    uint8_t* crow = g_codec + (size_t)(bN + ic) * NSEQ;

    if (ic >= nv) {
        for (int j = tid; j < nvp; j += 256) crow[j] = 0;
        int hh = tid >> 5, dd = tid & 31;
        g_q[((size_t)(b * NHEAD + hh) * NSEQ + ic) * HD + dd] = __float2bfloat16(0.f);
        g_k[((size_t)(b * NHEAD + hh) * NSEQ + ic) * HD + dd] = __float2bfloat16(0.f);
        g_vT[((size_t)(b * NHEAD + hh) * HD + dd) * NSEQ + ic] = __float2half(0.f);
        return;
    }
    int ri = g_rl[bN + ic];
    const int* er = et + (size_t)(bN + ri) * NSEQ;
    for (int jc = tid; jc < nvp; jc += 256) {
        uint8_t cv = 0;
        if (jc < nv) {
            int rj = g_rl[bN + jc];
            int e = er[rj];
            cv = (e != 0 || ri == rj) ? (uint8_t)(e + 1) : 0;
        }
        crow[jc] = cv;
    }
}

// ---------------- LN2 (compacted, guarded) ----------------
__global__ void ln2_kernel(const float* __restrict__ x,
                           const float* __restrict__ g,
                           const float* __restrict__ b,
                           bf16* __restrict__ y)
{
    __shared__ float red[8];
    __shared__ float stat[2];
    int row = blockIdx.x;
    if ((row & 2047) >= g_nvp[row >> 11]) return;
    ln_body(x, g, b, y, row, red, stat);
}

// ---------------- split-K merge + normalize (float4 vectorized) ------------
__global__ void __launch_bounds__(256)
merge_kernel()
{
    int idx = blockIdx.x * 256 + threadIdx.x;   // over ROWS*DIMD/4
    int rc = idx >> 6;
    int b = rc >> 11, rcl = rc & 2047;
    if (rcl >= g_nv[b]) return;
    int dim4 = idx & 63;
    int h = dim4 >> 3;
    int li = (b * NHEAD + h) * NSEQ + rcl;
    float l = g_l0[li] + g_l1[li];
    float inv = l > 0.f ? 1.f / l : 0.f;
    size_t o = (size_t)rc * DIMD + dim4 * 4;
    float4 a = *(const float4*)&g_o0[o];
    float4 c = *(const float4*)&g_o1[o];
    __nv_bfloat162 r0 = __floats2bfloat162_rn((a.x + c.x) * inv, (a.y + c.y) * inv);
    __nv_bfloat162 r1 = __floats2bfloat162_rn((a.z + c.z) * inv, (a.w + c.w) * inv);
    *(uint2*)&g_aoc[o] = make_uint2(*(uint32_t*)&r0, *(uint32_t*)&r1);
}

// ---------------- bf16 MMA GEMM, BK=64, NSTAGE-deep cp.async, ldmatrix -----
// MODE 0: qkv  MODE 1: proj  MODE 2: ffn1  MODE 3: ffn2
template<int BM, int BN, int KD, int NT, int MODE, int NSTAGE>
__global__ void __launch_bounds__(256, 2)
mma_gemm(const bf16* __restrict__ A, const bf16* __restrict__ Wt,
         const float* __restrict__ bias, const float* __restrict__ extra,
         float* __restrict__ outf, bf16* __restrict__ outb)
{
    constexpr int WM  = BM / 32;
    constexpr int WN  = 8 / WM;
    constexpr int WTN = BN / WN;
    constexpr int NTN = WTN / 8;
    constexpr int CB  = BN / 32;
    constexpr int NK  = KD / 64;

    int rm = blockIdx.y * BM, cn = blockIdx.x * BN;
    int bb = rm >> 11;
    if ((rm & 2047) >= g_nvp[bb]) return;
    int nv_b = g_nv[bb];
    int bN0 = bb << 11;

    extern __shared__ __align__(16) bf16 gsm[];
    bf16* As = gsm;
    bf16* Bs = gsm + NSTAGE * BM * 72;

    int t = threadIdx.x, lane = t & 31, warp = t >> 5;
    int gid = lane >> 2, tig = lane & 3;
    int gq = lane >> 3, wq = lane & 7;
    int wm = warp % WM, wn = warp / WM;
    const bf16* Bg = Wt + (size_t)cn * KD;

    const bf16* Asrc0;
    const bf16* Asrc1;
    if (MODE == 0) {
        int rl0 = g_rl[bN0 + (rm & 2047) + (t >> 3)];
        int rl1 = g_rl[bN0 + (rm & 2047) + (t >> 3) + 32];
        Asrc0 = A + (size_t)(bN0 + rl0) * KD;
        Asrc1 = A + (size_t)(bN0 + rl1) * KD;
    } else {
        Asrc0 = A + (size_t)(rm + (t >> 3)) * KD;
        Asrc1 = A + (size_t)(rm + (t >> 3) + 32) * KD;
    }

    uint32_t As_u = (uint32_t)__cvta_generic_to_shared(As);
    uint32_t Bs_u = (uint32_t)__cvta_generic_to_shared(Bs);
    uint32_t offA = (uint32_t)(((gq & 1) * 8 + wq) * 144 + (gq >> 1) * 16);
    uint32_t offB = (uint32_t)(((gq >> 1) * 8 + wq) * 144 + (gq & 1) * 16);

    float acc[2][NTN][4];
    #pragma unroll
    for (int mi = 0; mi < 2; ++mi)
        #pragma unroll
        for (int nt = 0; nt < NTN; ++nt)
            #pragma unroll
            for (int q = 0; q < 4; ++q) acc[mi][nt][q] = 0.f;

    int aoff = (t & 7) * 8;
    auto load_stage = [&](int k0, int st) {
        bf16* Asd = As + st * BM * 72;
        bf16* Bsd = Bs + st * BN * 72;
        cpasync16(&Asd[(t >> 3) * 72 + aoff],        Asrc0 + k0 + aoff);
        cpasync16(&Asd[((t >> 3) + 32) * 72 + aoff], Asrc1 + k0 + aoff);
        #pragma unroll
        for (int i = 0; i < CB; ++i) {
            int c = t + i * 256, row = c >> 3, off = (c & 7) * 8;
            cpasync16(&Bsd[row * 72 + off], Bg + (size_t)row * KD + k0 + off);
        }
        CP_COMMIT();
    };

    #pragma unroll
    for (int p = 0; p < NSTAGE - 1; ++p)
        if (p < NK) load_stage(p * 64, p);

    for (int i = 0; i < NK; ++i) {
        int st = i % NSTAGE;
        int infl = ((i + NSTAGE - 1 < NK) ? (i + NSTAGE - 1) : NK) - i - 1;
        if (NSTAGE >= 4 && infl >= 2) cp_wait<2>();
        else if (infl == 1) cp_wait<1>();
        else cp_wait<0>();
        __syncthreads();
        if (i + NSTAGE - 1 < NK) load_stage((i + NSTAGE - 1) * 64, (i + NSTAGE - 1) % NSTAGE);

        uint32_t Au = As_u + st * BM * 144;
        uint32_t Bu = Bs_u + st * BN * 144;
        #pragma unroll
        for (int ks = 0; ks < 4; ++ks) {
            uint32_t af[2][4];
            ldsm4(af[0], Au + (wm * 32     ) * 144 + ks * 32 + offA);
            ldsm4(af[1], Au + (wm * 32 + 16) * 144 + ks * 32 + offA);
            #pragma unroll
            for (int ntp = 0; ntp < NTN / 2; ++ntp) {
                uint32_t bbv[4];
                ldsm4(bbv, Bu + (wn * WTN + ntp * 16) * 144 + ks * 32 + offB);
                mma16(acc[0][2*ntp  ], af[0][0], af[0][1], af[0][2], af[0][3], bbv[0], bbv[1]);
                mma16(acc[1][2*ntp  ], af[1][0], af[1][1], af[1][2], af[1][3], bbv[0], bbv[1]);
                mma16(acc[0][2*ntp+1], af[0][0], af[0][1], af[0][2], af[0][3], bbv[2], bbv[3]);
                mma16(acc[1][2*ntp+1], af[1][0], af[1][1], af[1][2], af[1][3], bbv[2], bbv[3]);
            }
        }
    }
    __syncthreads();

    // ---- epilogue ----
    #pragma unroll
    for (int mi = 0; mi < 2; ++mi) {
        #pragma unroll
        for (int half_i = 0; half_i < 2; ++half_i) {
            int r = rm + wm * 32 + mi * 16 + gid + half_i * 8;
            int rcl = r & 2047;
            int norig = 0;
            if (MODE == 1 || MODE == 3) norig = g_rl[bN0 + rcl];
            #pragma unroll
            for (int nt = 0; nt < NTN; ++nt) {
                int c = cn + wn * WTN + nt * 8 + tig * 2;
                float bmul = (MODE == 0 && c < DIMD) ? QSCALE : 1.f;
                float v0 = acc[mi][nt][half_i * 2 + 0] + bias[c] * bmul;
                float v1 = acc[mi][nt][half_i * 2 + 1] + bias[c + 1] * bmul;
                if (MODE == 0) {
                    if (rcl < nv_b) {
                        int part = c >> 8, hh = (c >> 5) & 7, dd = c & 31;
                        if (part == 2) {
                            size_t base = ((size_t)(bb * NHEAD + hh) * HD + dd) * NSEQ + rcl;
                            g_vT[base]        = __float2half_rn(v0);
                            g_vT[base + NSEQ] = __float2half_rn(v1);
                        } else {
                            bf16* dst = (part == 0) ? g_q : g_k;
                            __nv_bfloat162 pv = __floats2bfloat162_rn(v0, v1);
                            *(__nv_bfloat162*)&dst[((size_t)(bb * NHEAD + hh) * NSEQ + rcl) * HD + dd] = pv;
                        }
                    }
                } else if (MODE == 1) {
                    float2 ex = *(const float2*)&extra[(size_t)(bN0 + norig) * NT + c];
                    *(float2*)&outf[(size_t)r * NT + c] = make_float2(ex.x + v0, ex.y + v1);
                } else if (MODE == 2) {
                    float g0 = 0.5f * v0 * (1.f + erff(v0 * 0.70710678118654752f));
                    float g1 = 0.5f * v1 * (1.f + erff(v1 * 0.70710678118654752f));
                    *(__nv_bfloat162*)&outb[(size_t)r * NT + c] = __floats2bfloat162_rn(g0, g1);
                } else {
                    if (rcl < nv_b) {
                        float2 ex = *(const float2*)&extra[(size_t)r * NT + c];
                        *(float2*)&outf[(size_t)(bN0 + norig) * NT + c] =
                            make_float2(ex.x + v0, ex.y + v1);
                    }
                }
            }
        }
    }
}

// ---------------- compacted flash attention, split-K x2, key-half warps ----
// 8 warps = 4 row-groups (32 rows) x 2 key-halves (64 keys). Halves smem BW.
__global__ void __launch_bounds__(256, 2)
attn_mma(const float* __restrict__ ebt)
{
    extern __shared__ __align__(16) bf16 smb[];
    bf16* Qs  = smb;                         // 128*40
    bf16* Ks0 = Qs + 5120;                   // 3 stages x 128*40
    half* Vs0 = (half*)(Ks0 + 3 * 5120);     // 3 stages x 40*136
    float* tbl2 = (float*)(Vs0 + 3 * 5440);  // 16 f32
    __half2* tblp = (__half2*)(tbl2 + 16);   // 2314 pair-bias entries
    float* comb = (float*)Ks0;               // reused after mainloop (128*41*4 B)

    int tid = threadIdx.x, lane = tid & 31, warp = tid >> 5;
    int gid = lane >> 2, tig = lane & 3;
    int gq = lane >> 3, wq = lane & 7;
    int bid = blockIdx.x;
    int h = bid & 7, rb = (bid >> 3) & 15, s = (bid >> 7) & 1, b = (bid >> 8) & 1;
    int r0 = rb * 128;
    const int bN = b * NSEQ;
    int rg = warp & 3, kh = warp >> 2;
    int rw = rg * 32;
    int kb0 = kh * 64;

    int nvp = g_nvp[b];
    if (r0 >= nvp) return;
    int ntiles = nvp >> 7;
    int nh = (ntiles + 1) >> 1;
    int lo = s ? nh : 0;
    int hi = s ? ntiles : nh;
    if (lo >= hi) return;

    const bf16* qptr = g_q  + ((size_t)(b * NHEAD + h) * NSEQ + r0) * HD;
    const bf16* kbh  = g_k  + (size_t)(b * NHEAD + h) * NSEQ * HD;
    const half* vT   = g_vT + (size_t)(b * NHEAD + h) * HD * NSEQ;

    uint32_t Qs_u = (uint32_t)__cvta_generic_to_shared(Qs);
    uint32_t Ks_u = (uint32_t)__cvta_generic_to_shared(Ks0);
    uint32_t Vs_u = (uint32_t)__cvta_generic_to_shared(Vs0);
    uint32_t offA = (uint32_t)(((gq & 1) * 8 + wq) * 80 + (gq >> 1) * 16);
    uint32_t offB = (uint32_t)(((gq >> 1) * 8 + wq) * 80 + (gq & 1) * 16);
    uint32_t offV = (uint32_t)(((gq >> 1) * 8 + wq) * 272 + (gq & 1) * 16);

    auto load_kv = [&](int kt, int st) {
        int j0 = kt * 128;
        bf16* Ksd = Ks0 + st * 5120;
        half* Vsd = Vs0 + st * 5440;
        #pragma unroll
        for (int i = 0; i < 2; ++i) {
            int c = tid + i * 256, row = c >> 2, off = (c & 3) * 8;
            cpasync16(&Ksd[row * 40 + off], kbh + (size_t)(j0 + row) * HD + off);
        }
        #pragma unroll
        for (int i = 0; i < 2; ++i) {
            int c = tid + i * 256, d = c >> 4, off = (c & 15) * 8;
            cpasync16(&Vsd[d * 136 + off], vT + (size_t)d * NSEQ + j0 + off);
        }
        CP_COMMIT();
    };

    load_kv(lo, 0);
    if (lo + 1 < hi) load_kv(lo + 1, 1);

    #pragma unroll
    for (int i = 0; i < 2; ++i) {
        int c = tid + i * 256, row = c >> 2, off = (c & 3) * 8;
        *(uint4*)&Qs[row * 40 + off] = *(const uint4*)(qptr + (size_t)row * HD + off);
    }
    for (int u = tid; u < 3 * 8 * 64; u += 256) {
        int stg = u / 512, rem = u % 512, rowe = rem / 64, col = rem % 64;
        uint32_t val = (rowe == 0) ? 0x3C003C00u : 0u;
        *(uint32_t*)&Vs0[stg * 5440 + (32 + rowe) * 136 + col * 2] = val;
    }
    if (tid < 16)
        tbl2[tid] = (tid == 0) ? -30000.f
                  : (tid < 10 ? ebt[(tid - 1) * NHEAD + h] * LOG2E : 0.f);
    __syncthreads();

    for (int idx = tid; idx < 2314; idx += 256)
        tblp[idx] = __floats2half2_rn(tbl2[idx & 15], tbl2[(idx >> 8) & 15]);
    __syncthreads();

    // Q fragments: 2 m-groups of 16 rows for this warp's 32 rows
    uint32_t qa[2][2][4];
    #pragma unroll
    for (int mg = 0; mg < 2; ++mg)
        #pragma unroll
        for (int ks = 0; ks < 2; ++ks)
            ldsm4(qa[mg][ks], Qs_u + (rw + mg * 16) * 80 + ks * 32 + offA);

    float oacc[2][5][4];
    #pragma unroll
    for (int mg = 0; mg < 2; ++mg)
        #pragma unroll
        for (int nt = 0; nt < 5; ++nt)
            #pragma unroll
            for (int q = 0; q < 4; ++q) oacc[mg][nt][q] = 0.f;

    const uint8_t* crow = g_codec + (size_t)(bN + r0 + rw + gid) * NSEQ + tig * 2;

    for (int kt = lo; kt < hi; ++kt) {
        int st = (kt - lo) % 3, j0 = kt * 128;
        if (kt + 1 < hi) cp_wait<1>(); else cp_wait<0>();
        __syncthreads();
        if (kt + 2 < hi) load_kv(kt + 2, (kt - lo + 2) % 3);

        uint32_t Ku = Ks_u + st * 10240;
        uint32_t Vu = Vs_u + st * 10880;

        #pragma unroll
        for (int ch = 0; ch < 2; ++ch) {
            int cb = kb0 + ch * 32;   // 32-key chunk base

            // prefetch edge codes for this chunk (4 rows x 4 n-tiles)
            uint32_t ccl[2][4];
            #pragma unroll
            for (int mg = 0; mg < 2; ++mg)
                #pragma unroll
                for (int nt = 0; nt < 4; ++nt) {
                    const uint8_t* p = crow + (size_t)(mg * 16) * NSEQ + j0 + cb + nt * 8;
                    uint32_t c0 = *(const unsigned short*)p;
                    uint32_t c1 = *(const unsigned short*)(p + 8 * NSEQ);
                    ccl[mg][nt] = c0 | (c1 << 16);
                }

            // ---- QK for 32 rows x 32 keys ----
            float sacc[2][4][4];
            #pragma unroll
            for (int mg = 0; mg < 2; ++mg)
                #pragma unroll
                for (int nt = 0; nt < 4; ++nt)
                    #pragma unroll
                    for (int q = 0; q < 4; ++q) sacc[mg][nt][q] = 0.f;
            #pragma unroll
            for (int ks = 0; ks < 2; ++ks) {
                #pragma unroll
                for (int ntp = 0; ntp < 2; ++ntp) {
                    uint32_t kb[4];
                    ldsm4(kb, Ku + (cb + ntp * 16) * 80 + ks * 32 + offB);
                    mma16(sacc[0][2*ntp  ], qa[0][ks][0], qa[0][ks][1], qa[0][ks][2], qa[0][ks][3], kb[0], kb[1]);
                    mma16(sacc[0][2*ntp+1], qa[0][ks][0], qa[0][ks][1], qa[0][ks][2], qa[0][ks][3], kb[2], kb[3]);
                    mma16(sacc[1][2*ntp  ], qa[1][ks][0], qa[1][ks][1], qa[1][ks][2], qa[1][ks][3], kb[0], kb[1]);
                    mma16(sacc[1][2*ntp+1], qa[1][ks][0], qa[1][ks][1], qa[1][ks][2], qa[1][ks][3], kb[2], kb[3]);
                }
            }

            // ---- exp + PV per 16-key subchunk ----
            #pragma unroll
            for (int ks2 = 0; ks2 < 2; ++ks2) {
                uint32_t vb[10];
                uint32_t vcol = cb * 2 + ks2 * 32;
                ldsm4(vb + 0, Vu +    0 + vcol + offV);
                ldsm4(vb + 4, Vu + 4352 + vcol + offV);
                ldsm2(vb + 8, Vu + 8704 + vcol + offV);
                #pragma unroll
                for (int mg = 0; mg < 2; ++mg) {
                    uint32_t pf[4];
                    {
                        uint32_t c = ccl[mg][2 * ks2];
                        __half2 s01 = __floats2half2_rn(sacc[mg][2*ks2][0], sacc[mg][2*ks2][1]);
                        __half2 s23 = __floats2half2_rn(sacc[mg][2*ks2][2], sacc[mg][2*ks2][3]);
                        s01 = __hadd2(s01, tblp[c & 0xffff]);
                        s23 = __hadd2(s23, tblp[c >> 16]);
                        pf[0] = hex2(*(uint32_t*)&s01);
                        pf[1] = hex2(*(uint32_t*)&s23);
                    }
                    {
                        uint32_t c = ccl[mg][2 * ks2 + 1];
                        __half2 s01 = __floats2half2_rn(sacc[mg][2*ks2+1][0], sacc[mg][2*ks2+1][1]);
                        __half2 s23 = __floats2half2_rn(sacc[mg][2*ks2+1][2], sacc[mg][2*ks2+1][3]);
                        s01 = __hadd2(s01, tblp[c & 0xffff]);
                        s23 = __hadd2(s23, tblp[c >> 16]);
                        pf[2] = hex2(*(uint32_t*)&s01);
                        pf[3] = hex2(*(uint32_t*)&s23);
                    }
                    #pragma unroll
                    for (int ntv = 0; ntv < 5; ++ntv)
                        mma16h(oacc[mg][ntv], pf[0], pf[1], pf[2], pf[3],
                               vb[2*ntv], vb[2*ntv+1]);
                }
            }
        }
    }

    // ---- combine key-halves through smem (K buffers retired) ----
    __syncthreads();
    if (kh == 1) {
        float* cw = comb + (rw + lane) * 41;
        #pragma unroll
        for (int mg = 0; mg < 2; ++mg)
            #pragma unroll
            for (int nt = 0; nt < 5; ++nt)
                #pragma unroll
                for (int q = 0; q < 4; ++q)
                    cw[mg * 20 + nt * 4 + q] = oacc[mg][nt][q];
    }
    __syncthreads();
    if (kh == 1) return;

    {
        const float* cr = comb + (rw + lane) * 41;
        #pragma unroll
        for (int mg = 0; mg < 2; ++mg)
            #pragma unroll
            for (int nt = 0; nt < 5; ++nt)
                #pragma unroll
                for (int q = 0; q < 4; ++q)
                    oacc[mg][nt][q] += cr[mg * 20 + nt * 4 + q];
    }

    // ---- write split partials (unnormalized) ----
    float* pl = s ? g_l1 : g_l0;
    float* po = s ? g_o1 : g_o0;
    float* pod = po + (size_t)(bN + r0) * DIMD + h * HD;
    #pragma unroll
    for (int mg = 0; mg < 2; ++mg) {
        int rloc = rw + mg * 16 + gid;
        if (tig == 0) {
            int li = (b * NHEAD + h) * NSEQ + r0 + rloc;
            pl[li]     = oacc[mg][4][0];
            pl[li + 8] = oacc[mg][4][2];
        }
        #pragma unroll
        for (int nt = 0; nt < 4; ++nt) {
            int d = nt * 8 + tig * 2;
            *(float2*)&pod[(size_t)(rloc    ) * DIMD + d] =
                make_float2(oacc[mg][nt][0], oacc[mg][nt][1]);
            *(float2*)&pod[(size_t)(rloc + 8) * DIMD + d] =
                make_float2(oacc[mg][nt][2], oacc[mg][nt][3]);
        }
    }
}

// ---------------- launch ----------------
static void* sym_addr(const void* sym)
{
    void* p = nullptr;
    cudaGetSymbolAddress(&p, sym);
    return p;
}

extern "C" void kernel_launch(void* const* d_in, const int* in_sizes, int n_in,
                              void* d_out, int out_size)
{
    const float* x      = (const float*)d_in[0];
    const int*   etyp   = (const int*)  d_in[1];
    const int*   nmask  = (const int*)  d_in[2];
    const float* qkv_w  = (const float*)d_in[3];
    const float* qkv_b  = (const float*)d_in[4];
    const float* proj_w = (const float*)d_in[5];
    const float* proj_b = (const float*)d_in[6];
    const float* ebt    = (const float*)d_in[7];
    const float* ln1_g  = (const float*)d_in[8];
    const float* ln1_b  = (const float*)d_in[9];
    const float* ln2_g  = (const float*)d_in[10];
    const float* ln2_b  = (const float*)d_in[11];
    const float* ffn_w1 = (const float*)d_in[12];
    const float* ffn_b1 = (const float*)d_in[13];
    const float* ffn_w2 = (const float*)d_in[14];
    const float* ffn_b2 = (const float*)d_in[15];
    float* out = (float*)d_out;

    bf16*  ph    = (bf16*) sym_addr(g_h);
    bf16*  paoc  = (bf16*) sym_addr(g_aoc);
    float* px1c  = (float*)sym_addr(g_x1c);
    bf16*  ph2c  = (bf16*) sym_addr(g_h2c);
    bf16*  pmidc = (bf16*) sym_addr(g_midc);
    bf16*  pwqkv = (bf16*) sym_addr(g_wqkv);
    bf16*  pwproj= (bf16*) sym_addr(g_wproj);
    bf16*  pwf1  = (bf16*) sym_addr(g_wf1);
    bf16*  pwf2  = (bf16*) sym_addr(g_wf2);

    const int ATTN_SMEM  = 10240 + 30720 + 32640 + 64 + 9600;   // 83264
    const int GSM3_64_128 = 3 * (64 * 72 + 128 * 72) * 2;       // 82944
    const int GSM4_64_64  = 4 * (64 * 72 + 64 * 72) * 2;        // 73728
    cudaFuncSetAttribute(attn_mma, cudaFuncAttributeMaxDynamicSharedMemorySize, ATTN_SMEM);
    cudaFuncSetAttribute(mma_gemm<64,128,DIMD,3*DIMD,0,3>, cudaFuncAttributeMaxDynamicSharedMemorySize, GSM3_64_128);
    cudaFuncSetAttribute(mma_gemm<64,64,DIMD,DIMD,1,4>,    cudaFuncAttributeMaxDynamicSharedMemorySize, GSM4_64_64);
    cudaFuncSetAttribute(mma_gemm<64,128,DIMD,FFD,2,3>,    cudaFuncAttributeMaxDynamicSharedMemorySize, GSM3_64_128);
    cudaFuncSetAttribute(mma_gemm<64,64,FFD,DIMD,3,4>,     cudaFuncAttributeMaxDynamicSharedMemorySize, GSM4_64_64);

    // 1) setup: weight convert + LN1(valid) + masked-row copy + mask scan
    setup_kernel<<<768 + 2 * ROWS + BNUM, 256>>>(qkv_w, proj_w, ffn_w1, ffn_w2,
                                                 nmask, x, ln1_g, ln1_b, out);
    // 2) compacted codes + pad zeroing (high-occupancy, no smem)
    gather_kernel<<<dim3(NSEQ, BNUM), 256>>>(etyp);
    // 3) QKV GEMM (64x128, rows gathered via rowlist, compacted scatter)
    mma_gemm<64, 128, DIMD, 3*DIMD, 0, 3><<<dim3(6, 64), 256, GSM3_64_128>>>(
        ph, pwqkv, qkv_b, nullptr, nullptr, nullptr);
    // 4) attention, split-K x2, key-half warps, fp32 partials
    attn_mma<<<512, 256, ATTN_SMEM>>>(ebt);
    // 5) merge + normalize -> compacted bf16 (float4 vectorized)
    merge_kernel<<<ROWS * DIMD / 1024, 256>>>();
    // 6) proj + residual -> x1c (compacted, 64x64 4-stage)
    mma_gemm<64, 64, DIMD, DIMD, 1, 4><<<dim3(4, 64), 256, GSM4_64_64>>>(
        paoc, pwproj, proj_b, x, px1c, nullptr);
    // 7) LN2 (compacted)
    ln2_kernel<<<ROWS, 256>>>(px1c, ln2_g, ln2_b, ph2c);
    // 8) FFN1 + GELU (compacted, 64x128 3-stage)
    mma_gemm<64, 128, DIMD, FFD, 2, 3><<<dim3(8, 64), 256, GSM3_64_128>>>(
        ph2c, pwf1, ffn_b1, nullptr, nullptr, pmidc);
    // 9) FFN2 + residual, scatter to out via rowlist (64x64 4-stage)
    mma_gemm<64, 64, FFD, DIMD, 3, 4><<<dim3(4, 64), 256, GSM4_64_64>>>(
        pmidc, pwf2, ffn_b2, px1c, out, nullptr);
}